// round 1
// baseline (speedup 1.0000x reference)
#include <cuda_runtime.h>
#include <math.h>

// Problem constants: B=8, NQ=NK=1024, D=512, H=8, dh=64
#define BATCH 8
#define NQ 1024
#define NK 1024
#define DIM 512
#define HEADS 8
#define DH 64
#define BH (BATCH*HEADS)          // 64
#define MROWS (BATCH*NQ)          // 8192

// ---------------- scratch (device globals; allocation-free) ----------------
__device__ float g_q[BH * NK * DH];            // (bh, n, d)  16 MB
__device__ float g_k[BH * NK * DH];
__device__ float g_v[BH * NK * DH];
__device__ float g_S[(size_t)BH * NQ * NK];    // 256 MB scores
__device__ float g_O[MROWS * DIM];             // attention out (B,NQ,512)
__device__ float g_X[MROWS * DIM];             // post-LN0
__device__ float g_U[MROWS * DIM];             // X + relu(X@Wo+bo)

// ---------------- reductions ----------------
__device__ __forceinline__ float warpMax(float v) {
    #pragma unroll
    for (int o = 16; o > 0; o >>= 1) v = fmaxf(v, __shfl_xor_sync(0xffffffffu, v, o));
    return v;
}
__device__ __forceinline__ float warpSum(float v) {
    #pragma unroll
    for (int o = 16; o > 0; o >>= 1) v += __shfl_xor_sync(0xffffffffu, v, o);
    return v;
}

// ---------------- projection GEMM: C = A(M,512) @ W(512,512) + bias --------
// Output written in head layout: g_{q,k,v}[(b*H+h)*1024 + n][d]
// Tiles: 64x64, BK=16, 256 threads, 4x4 per thread.
__global__ void gemm_proj(const float* __restrict__ A,
                          const float* __restrict__ W,
                          const float* __restrict__ bias, int sel)
{
    __shared__ float AsT[16][64];
    __shared__ float Bs[16][64];
    const int n0 = blockIdx.x * 64;
    const int m0 = blockIdx.y * 64;
    const int tid = threadIdx.x;
    const int tx = tid & 15, ty = tid >> 4;
    float acc[4][4] = {};

    for (int k0 = 0; k0 < 512; k0 += 16) {
        int r = tid >> 2, c4 = (tid & 3) << 2;
        float4 a = *(const float4*)(A + (size_t)(m0 + r) * 512 + k0 + c4);
        AsT[c4 + 0][r] = a.x; AsT[c4 + 1][r] = a.y;
        AsT[c4 + 2][r] = a.z; AsT[c4 + 3][r] = a.w;
        int br = tid >> 4, bc = (tid & 15) << 2;
        *(float4*)&Bs[br][bc] = *(const float4*)(W + (size_t)(k0 + br) * 512 + n0 + bc);
        __syncthreads();
        #pragma unroll
        for (int k = 0; k < 16; k++) {
            float af[4], bf[4];
            *(float4*)af = *(const float4*)&AsT[k][ty * 4];
            *(float4*)bf = *(const float4*)&Bs[k][tx * 4];
            #pragma unroll
            for (int i = 0; i < 4; i++)
                #pragma unroll
                for (int j = 0; j < 4; j++) acc[i][j] += af[i] * bf[j];
        }
        __syncthreads();
    }

    float* outp = (sel == 0) ? g_q : (sel == 1) ? g_k : g_v;
    #pragma unroll
    for (int i = 0; i < 4; i++) {
        int m = m0 + ty * 4 + i;
        int b = m >> 10, n = m & 1023;
        #pragma unroll
        for (int j = 0; j < 4; j++) {
            int col = n0 + tx * 4 + j;
            int h = col >> 6, d = col & 63;
            outp[(((size_t)(b * HEADS + h)) * 1024 + n) * 64 + d] = acc[i][j] + bias[col];
        }
    }
}

// ---------------- scores: S[bh,i,j] = scale * q_i . k_j  (mask -> -1e4) ----
__global__ void attn_scores(const int* __restrict__ mask)
{
    __shared__ float qsT[64][64];
    __shared__ float ksT[64][64];
    const int bh = blockIdx.z;
    const int b = bh >> 3;
    const int i0 = blockIdx.y * 64, j0 = blockIdx.x * 64;
    const int tid = threadIdx.x;
    const float* qp = g_q + ((size_t)bh * 1024 + i0) * 64;
    const float* kp = g_k + ((size_t)bh * 1024 + j0) * 64;

    #pragma unroll
    for (int it = 0; it < 4; it++) {
        int e = tid + it * 256;
        int r = e >> 4, c4 = (e & 15) << 2;
        float4 a = *(const float4*)(qp + r * 64 + c4);
        qsT[c4 + 0][r] = a.x; qsT[c4 + 1][r] = a.y;
        qsT[c4 + 2][r] = a.z; qsT[c4 + 3][r] = a.w;
        float4 kk = *(const float4*)(kp + r * 64 + c4);
        ksT[c4 + 0][r] = kk.x; ksT[c4 + 1][r] = kk.y;
        ksT[c4 + 2][r] = kk.z; ksT[c4 + 3][r] = kk.w;
    }
    __syncthreads();

    const int tx = tid & 15, ty = tid >> 4;
    float acc[4][4] = {};
    #pragma unroll 8
    for (int d = 0; d < 64; d++) {
        float af[4], bf[4];
        *(float4*)af = *(const float4*)&qsT[d][ty * 4];
        *(float4*)bf = *(const float4*)&ksT[d][tx * 4];
        #pragma unroll
        for (int i = 0; i < 4; i++)
            #pragma unroll
            for (int j = 0; j < 4; j++) acc[i][j] += af[i] * bf[j];
    }

    const float scale = 0.044194173824159216f; // 1/sqrt(512)
    #pragma unroll
    for (int i = 0; i < 4; i++) {
        int qi = i0 + ty * 4 + i;
        float* sp = g_S + ((size_t)bh * 1024 + qi) * 1024 + j0;
        #pragma unroll
        for (int j = 0; j < 4; j++) {
            int kj = j0 + tx * 4 + j;
            float val = (mask[b * 1024 + kj] == 0) ? -10000.0f : acc[i][j] * scale;
            sp[tx * 4 + j] = val;
        }
    }
}

// ---------------- softmax over rows of 1024 --------------------------------
__global__ void softmax_rows()
{
    __shared__ float red[8];
    float* p = g_S + (size_t)blockIdx.x * 1024;
    const int t = threadIdx.x;
    float v[4];
    #pragma unroll
    for (int i = 0; i < 4; i++) v[i] = p[t + 256 * i];

    float m = fmaxf(fmaxf(v[0], v[1]), fmaxf(v[2], v[3]));
    m = warpMax(m);
    if ((t & 31) == 0) red[t >> 5] = m;
    __syncthreads();
    m = red[0];
    #pragma unroll
    for (int i = 1; i < 8; i++) m = fmaxf(m, red[i]);
    __syncthreads();

    float s = 0.f;
    #pragma unroll
    for (int i = 0; i < 4; i++) { v[i] = __expf(v[i] - m); s += v[i]; }
    s = warpSum(s);
    if ((t & 31) == 0) red[t >> 5] = s;
    __syncthreads();
    s = 0.f;
    #pragma unroll
    for (int i = 0; i < 8; i++) s += red[i];
    float r = 1.0f / s;
    #pragma unroll
    for (int i = 0; i < 4; i++) p[t + 256 * i] = v[i] * r;
}

// ---------------- PV: O = q + A @ v  (head layout -> (B,NQ,512)) -----------
__global__ void attn_pv()
{
    __shared__ float AsT[16][64];
    __shared__ float Bs[16][64];
    const int bh = blockIdx.y;
    const int i0 = blockIdx.x * 64;
    const int b = bh >> 3, h = bh & 7;
    const int tid = threadIdx.x;
    const int tx = tid & 15, ty = tid >> 4;
    float acc[4][4] = {};
    const float* Sp = g_S + ((size_t)bh * 1024 + i0) * 1024;
    const float* vp = g_v + (size_t)bh * 1024 * 64;

    for (int n0 = 0; n0 < 1024; n0 += 16) {
        int r = tid >> 2, c4 = (tid & 3) << 2;
        float4 a = *(const float4*)(Sp + (size_t)r * 1024 + n0 + c4);
        AsT[c4 + 0][r] = a.x; AsT[c4 + 1][r] = a.y;
        AsT[c4 + 2][r] = a.z; AsT[c4 + 3][r] = a.w;
        int nr = tid >> 4, dc = (tid & 15) << 2;
        *(float4*)&Bs[nr][dc] = *(const float4*)(vp + (size_t)(n0 + nr) * 64 + dc);
        __syncthreads();
        #pragma unroll
        for (int k = 0; k < 16; k++) {
            float af[4], bf[4];
            *(float4*)af = *(const float4*)&AsT[k][ty * 4];
            *(float4*)bf = *(const float4*)&Bs[k][tx * 4];
            #pragma unroll
            for (int i = 0; i < 4; i++)
                #pragma unroll
                for (int j = 0; j < 4; j++) acc[i][j] += af[i] * bf[j];
        }
        __syncthreads();
    }

    #pragma unroll
    for (int i = 0; i < 4; i++) {
        int qi = i0 + ty * 4 + i;
        const float* qrow = g_q + ((size_t)bh * 1024 + qi) * 64;
        float* orow = g_O + ((size_t)(b * 1024 + qi)) * 512 + h * 64;
        #pragma unroll
        for (int j = 0; j < 4; j++) {
            int d = tx * 4 + j;
            orow[d] = acc[i][j] + qrow[d];
        }
    }
}

// ---------------- LayerNorm over rows of 512 -------------------------------
// sel==0: g_O -> g_X ; sel==1: g_U -> extout
__global__ void ln_kernel(const float* __restrict__ gg, const float* __restrict__ bb,
                          float* __restrict__ extout, int sel)
{
    __shared__ float red[4];
    const float* in = (sel == 0) ? g_O : g_U;
    float* out = (sel == 0) ? g_X : extout;
    const int row = blockIdx.x, t = threadIdx.x;
    const float* p = in + (size_t)row * 512;
    float v[4];
    #pragma unroll
    for (int i = 0; i < 4; i++) v[i] = p[t + 128 * i];

    float s = v[0] + v[1] + v[2] + v[3];
    s = warpSum(s);
    if ((t & 31) == 0) red[t >> 5] = s;
    __syncthreads();
    s = red[0] + red[1] + red[2] + red[3];
    float mean = s * (1.f / 512.f);
    __syncthreads();

    float ss = 0.f;
    #pragma unroll
    for (int i = 0; i < 4; i++) { float d = v[i] - mean; ss += d * d; }
    ss = warpSum(ss);
    if ((t & 31) == 0) red[t >> 5] = ss;
    __syncthreads();
    ss = red[0] + red[1] + red[2] + red[3];
    float inv = rsqrtf(ss * (1.f / 512.f) + 1e-5f);

    #pragma unroll
    for (int i = 0; i < 4; i++) {
        int c = t + 128 * i;
        out[(size_t)row * 512 + c] = (v[i] - mean) * inv * gg[c] + bb[c];
    }
}

// ---------------- output MLP: U = X + relu(X@Wo + bo) ----------------------
__global__ void gemm_out(const float* __restrict__ W, const float* __restrict__ bias)
{
    __shared__ float AsT[16][64];
    __shared__ float Bs[16][64];
    const int n0 = blockIdx.x * 64;
    const int m0 = blockIdx.y * 64;
    const int tid = threadIdx.x;
    const int tx = tid & 15, ty = tid >> 4;
    float acc[4][4] = {};

    for (int k0 = 0; k0 < 512; k0 += 16) {
        int r = tid >> 2, c4 = (tid & 3) << 2;
        float4 a = *(const float4*)(g_X + (size_t)(m0 + r) * 512 + k0 + c4);
        AsT[c4 + 0][r] = a.x; AsT[c4 + 1][r] = a.y;
        AsT[c4 + 2][r] = a.z; AsT[c4 + 3][r] = a.w;
        int br = tid >> 4, bc = (tid & 15) << 2;
        *(float4*)&Bs[br][bc] = *(const float4*)(W + (size_t)(k0 + br) * 512 + n0 + bc);
        __syncthreads();
        #pragma unroll
        for (int k = 0; k < 16; k++) {
            float af[4], bf[4];
            *(float4*)af = *(const float4*)&AsT[k][ty * 4];
            *(float4*)bf = *(const float4*)&Bs[k][tx * 4];
            #pragma unroll
            for (int i = 0; i < 4; i++)
                #pragma unroll
                for (int j = 0; j < 4; j++) acc[i][j] += af[i] * bf[j];
        }
        __syncthreads();
    }

    #pragma unroll
    for (int i = 0; i < 4; i++) {
        int m = m0 + ty * 4 + i;
        #pragma unroll
        for (int j = 0; j < 4; j++) {
            int c = n0 + tx * 4 + j;
            float y = acc[i][j] + bias[c];
            float xv = g_X[(size_t)m * 512 + c];
            g_U[(size_t)m * 512 + c] = xv + fmaxf(y, 0.f);
        }
    }
}

// ---------------- launch ----------------------------------------------------
extern "C" void kernel_launch(void* const* d_in, const int* in_sizes, int n_in,
                              void* d_out, int out_size)
{
    const float* Q    = (const float*)d_in[0];
    const float* K    = (const float*)d_in[1];
    const int*   mask = (const int*)  d_in[2];
    const float* Wq   = (const float*)d_in[3];
    const float* bq   = (const float*)d_in[4];
    const float* Wk   = (const float*)d_in[5];
    const float* bk   = (const float*)d_in[6];
    const float* Wv   = (const float*)d_in[7];
    const float* bv   = (const float*)d_in[8];
    const float* Wo   = (const float*)d_in[9];
    const float* bo   = (const float*)d_in[10];
    const float* g0   = (const float*)d_in[11];
    const float* b0   = (const float*)d_in[12];
    const float* g1   = (const float*)d_in[13];
    const float* b1   = (const float*)d_in[14];
    float* out = (float*)d_out;

    dim3 gp(DIM / 64, MROWS / 64);          // (8, 128)
    gemm_proj<<<gp, 256>>>(Q, Wq, bq, 0);
    gemm_proj<<<gp, 256>>>(K, Wk, bk, 1);
    gemm_proj<<<gp, 256>>>(K, Wv, bv, 2);

    dim3 gs(NK / 64, NQ / 64, BH);          // (16, 16, 64)
    attn_scores<<<gs, 256>>>(mask);

    softmax_rows<<<BH * NQ, 256>>>();       // 65536 rows

    dim3 gpv(NQ / 64, BH);                  // (16, 64)
    attn_pv<<<gpv, 256>>>();

    ln_kernel<<<MROWS, 128>>>(g0, b0, nullptr, 0);
    gemm_out<<<gp, 256>>>(Wo, bo);
    ln_kernel<<<MROWS, 128>>>(g1, b1, out, 1);
}

// round 2
// speedup vs baseline: 1.4084x; 1.4084x over previous
#include <cuda_runtime.h>
#include <math.h>

// Problem constants: B=8, NQ=NK=1024, D=512, H=8, dh=64
#define BATCH 8
#define NQ 1024
#define NK 1024
#define DIM 512
#define HEADS 8
#define DH 64
#define BH (BATCH*HEADS)          // 64
#define MROWS (BATCH*NQ)          // 8192

// ---------------- scratch (device globals; allocation-free) ----------------
__device__ float g_q[BH * NK * DH];            // (bh, n, d)  16 MB
__device__ float g_k[BH * NK * DH];
__device__ float g_v[BH * NK * DH];
__device__ float g_O[MROWS * DIM];             // attention out (B,NQ,512)
__device__ float g_X[MROWS * DIM];             // post-LN0
__device__ float g_U[MROWS * DIM];             // X + relu(X@Wo+bo)

// ---------------- helpers ----------------
__device__ __forceinline__ float warpSum(float v) {
    #pragma unroll
    for (int o = 16; o > 0; o >>= 1) v += __shfl_xor_sync(0xffffffffu, v, o);
    return v;
}

__device__ __forceinline__ unsigned f2tf(float x) {
    unsigned u;
    asm("cvt.rna.tf32.f32 %0, %1;" : "=r"(u) : "f"(x));
    return u;
}

__device__ __forceinline__ void mma_tf32(float c[4],
                                         unsigned a0, unsigned a1, unsigned a2, unsigned a3,
                                         unsigned b0, unsigned b1)
{
    asm volatile(
        "mma.sync.aligned.m16n8k8.row.col.f32.tf32.tf32.f32 "
        "{%0,%1,%2,%3}, {%4,%5,%6,%7}, {%8,%9}, {%0,%1,%2,%3};\n"
        : "+f"(c[0]), "+f"(c[1]), "+f"(c[2]), "+f"(c[3])
        : "r"(a0), "r"(a1), "r"(a2), "r"(a3), "r"(b0), "r"(b1));
}

// ---------------- projection GEMM: C = A(M,512) @ W(512,512) + bias --------
// Output written in head layout: g_{q,k,v}[(b*H+h)*1024 + n][d]
__global__ void gemm_proj(const float* __restrict__ A,
                          const float* __restrict__ W,
                          const float* __restrict__ bias, int sel)
{
    __shared__ float AsT[16][64];
    __shared__ float Bs[16][64];
    const int n0 = blockIdx.x * 64;
    const int m0 = blockIdx.y * 64;
    const int tid = threadIdx.x;
    const int tx = tid & 15, ty = tid >> 4;
    float acc[4][4] = {};

    for (int k0 = 0; k0 < 512; k0 += 16) {
        int r = tid >> 2, c4 = (tid & 3) << 2;
        float4 a = *(const float4*)(A + (size_t)(m0 + r) * 512 + k0 + c4);
        AsT[c4 + 0][r] = a.x; AsT[c4 + 1][r] = a.y;
        AsT[c4 + 2][r] = a.z; AsT[c4 + 3][r] = a.w;
        int br = tid >> 4, bc = (tid & 15) << 2;
        *(float4*)&Bs[br][bc] = *(const float4*)(W + (size_t)(k0 + br) * 512 + n0 + bc);
        __syncthreads();
        #pragma unroll
        for (int k = 0; k < 16; k++) {
            float af[4], bf[4];
            *(float4*)af = *(const float4*)&AsT[k][ty * 4];
            *(float4*)bf = *(const float4*)&Bs[k][tx * 4];
            #pragma unroll
            for (int i = 0; i < 4; i++)
                #pragma unroll
                for (int j = 0; j < 4; j++) acc[i][j] += af[i] * bf[j];
        }
        __syncthreads();
    }

    float* outp = (sel == 0) ? g_q : (sel == 1) ? g_k : g_v;
    #pragma unroll
    for (int i = 0; i < 4; i++) {
        int m = m0 + ty * 4 + i;
        int b = m >> 10, n = m & 1023;
        #pragma unroll
        for (int j = 0; j < 4; j++) {
            int col = n0 + tx * 4 + j;
            int h = col >> 6, d = col & 63;
            outp[(((size_t)(b * HEADS + h)) * 1024 + n) * 64 + d] = acc[i][j] + bias[col];
        }
    }
}

// ---------------- fused flash attention ------------------------------------
// Per block: one (bh, 128-q-row) tile. 8 warps x 16 rows each.
// Streams K/V in 32-key chunks; online softmax; O = q + softmax(S) @ v.
__global__ void __launch_bounds__(256) flash_attn(const int* __restrict__ mask)
{
    __shared__ unsigned KsT[64][33];       // K^T chunk: [d][n], conflict-free for B-frag reads
    __shared__ unsigned Vs[32][65];        // V chunk:   [kk][d]
    __shared__ unsigned Ps[8][16][33];     // per-warp P tile (16x32)
    __shared__ int ms[32];                 // mask chunk

    const int bh = blockIdx.y;
    const int b = bh >> 3, h = bh & 7;
    const int i0 = blockIdx.x * 128;
    const int tid = threadIdx.x;
    const int warp = tid >> 5, lane = tid & 31;
    const int g = lane >> 2, t = lane & 3;

    // Q fragments for this warp's 16 rows (rows g, g+8), all 64 d-cols (8 k-steps)
    const float* qbase = g_q + ((size_t)bh * 1024 + i0 + warp * 16) * 64;
    unsigned qa[8][4];
    #pragma unroll
    for (int k = 0; k < 8; k++) {
        qa[k][0] = f2tf(qbase[(g    ) * 64 + k * 8 + t    ]);
        qa[k][1] = f2tf(qbase[(g + 8) * 64 + k * 8 + t    ]);
        qa[k][2] = f2tf(qbase[(g    ) * 64 + k * 8 + t + 4]);
        qa[k][3] = f2tf(qbase[(g + 8) * 64 + k * 8 + t + 4]);
    }

    float oacc[8][4];
    #pragma unroll
    for (int n = 0; n < 8; n++)
        #pragma unroll
        for (int j = 0; j < 4; j++) oacc[n][j] = 0.f;
    float mrow0 = -1e30f, mrow1 = -1e30f;
    float lrow0 = 0.f,    lrow1 = 0.f;

    const float* kbase = g_k + (size_t)bh * 1024 * 64;
    const float* vbase = g_v + (size_t)bh * 1024 * 64;
    const float scale = 0.044194173824159216f; // 1/sqrt(512)

    for (int j0 = 0; j0 < 1024; j0 += 32) {
        __syncthreads();   // previous iteration's smem reads done
        {
            int r = tid >> 3;            // key index within chunk 0..31
            int c = (tid & 7) * 8;       // d base 0..56
            const float4* kp = (const float4*)(kbase + (size_t)(j0 + r) * 64 + c);
            const float4* vp = (const float4*)(vbase + (size_t)(j0 + r) * 64 + c);
            float4 k0 = kp[0], k1 = kp[1];
            float4 v0 = vp[0], v1 = vp[1];
            KsT[c + 0][r] = f2tf(k0.x); KsT[c + 1][r] = f2tf(k0.y);
            KsT[c + 2][r] = f2tf(k0.z); KsT[c + 3][r] = f2tf(k0.w);
            KsT[c + 4][r] = f2tf(k1.x); KsT[c + 5][r] = f2tf(k1.y);
            KsT[c + 6][r] = f2tf(k1.z); KsT[c + 7][r] = f2tf(k1.w);
            Vs[r][c + 0] = f2tf(v0.x); Vs[r][c + 1] = f2tf(v0.y);
            Vs[r][c + 2] = f2tf(v0.z); Vs[r][c + 3] = f2tf(v0.w);
            Vs[r][c + 4] = f2tf(v1.x); Vs[r][c + 5] = f2tf(v1.y);
            Vs[r][c + 6] = f2tf(v1.z); Vs[r][c + 7] = f2tf(v1.w);
        }
        if (tid < 32) ms[tid] = mask[b * 1024 + j0 + tid];
        __syncthreads();

        // S = Q @ K^T for this warp's 16 rows x 32 chunk cols
        float sc[4][4];
        #pragma unroll
        for (int n = 0; n < 4; n++)
            #pragma unroll
            for (int j = 0; j < 4; j++) sc[n][j] = 0.f;
        #pragma unroll
        for (int k = 0; k < 8; k++) {
            #pragma unroll
            for (int n = 0; n < 4; n++) {
                unsigned b0 = KsT[k * 8 + t    ][n * 8 + g];
                unsigned b1 = KsT[k * 8 + t + 4][n * 8 + g];
                mma_tf32(sc[n], qa[k][0], qa[k][1], qa[k][2], qa[k][3], b0, b1);
            }
        }

        // mask + scale
        float mx0 = -1e30f, mx1 = -1e30f;
        #pragma unroll
        for (int n = 0; n < 4; n++) {
            int j = n * 8 + 2 * t;
            float v0 = ms[j]     ? sc[n][0] * scale : -10000.0f;
            float v1 = ms[j + 1] ? sc[n][1] * scale : -10000.0f;
            float v2 = ms[j]     ? sc[n][2] * scale : -10000.0f;
            float v3 = ms[j + 1] ? sc[n][3] * scale : -10000.0f;
            sc[n][0] = v0; sc[n][1] = v1; sc[n][2] = v2; sc[n][3] = v3;
            mx0 = fmaxf(mx0, fmaxf(v0, v1));
            mx1 = fmaxf(mx1, fmaxf(v2, v3));
        }
        mx0 = fmaxf(mx0, __shfl_xor_sync(0xffffffffu, mx0, 1));
        mx0 = fmaxf(mx0, __shfl_xor_sync(0xffffffffu, mx0, 2));
        mx1 = fmaxf(mx1, __shfl_xor_sync(0xffffffffu, mx1, 1));
        mx1 = fmaxf(mx1, __shfl_xor_sync(0xffffffffu, mx1, 2));

        float mn0 = fmaxf(mrow0, mx0), mn1 = fmaxf(mrow1, mx1);
        float f0 = __expf(mrow0 - mn0), f1 = __expf(mrow1 - mn1);
        float s0 = 0.f, s1 = 0.f;
        #pragma unroll
        for (int n = 0; n < 4; n++) {
            float p0 = __expf(sc[n][0] - mn0);
            float p1 = __expf(sc[n][1] - mn0);
            float p2 = __expf(sc[n][2] - mn1);
            float p3 = __expf(sc[n][3] - mn1);
            s0 += p0 + p1; s1 += p2 + p3;
            Ps[warp][g    ][n * 8 + 2 * t    ] = f2tf(p0);
            Ps[warp][g    ][n * 8 + 2 * t + 1] = f2tf(p1);
            Ps[warp][g + 8][n * 8 + 2 * t    ] = f2tf(p2);
            Ps[warp][g + 8][n * 8 + 2 * t + 1] = f2tf(p3);
        }
        s0 += __shfl_xor_sync(0xffffffffu, s0, 1);
        s0 += __shfl_xor_sync(0xffffffffu, s0, 2);
        s1 += __shfl_xor_sync(0xffffffffu, s1, 1);
        s1 += __shfl_xor_sync(0xffffffffu, s1, 2);

        lrow0 = lrow0 * f0 + s0;
        lrow1 = lrow1 * f1 + s1;
        mrow0 = mn0; mrow1 = mn1;
        #pragma unroll
        for (int n = 0; n < 8; n++) {
            oacc[n][0] *= f0; oacc[n][1] *= f0;
            oacc[n][2] *= f1; oacc[n][3] *= f1;
        }
        __syncwarp();

        // O += P @ V  (per-warp: A = own P tile 16x32, B = V chunk 32x64)
        #pragma unroll
        for (int k = 0; k < 4; k++) {
            unsigned a0 = Ps[warp][g    ][k * 8 + t    ];
            unsigned a1 = Ps[warp][g + 8][k * 8 + t    ];
            unsigned a2 = Ps[warp][g    ][k * 8 + t + 4];
            unsigned a3 = Ps[warp][g + 8][k * 8 + t + 4];
            #pragma unroll
            for (int n = 0; n < 8; n++) {
                unsigned b0 = Vs[k * 8 + t    ][n * 8 + g];
                unsigned b1 = Vs[k * 8 + t + 4][n * 8 + g];
                mma_tf32(oacc[n], a0, a1, a2, a3, b0, b1);
            }
        }
        __syncwarp();
    }

    // epilogue: O/l + q residual -> g_O (B,NQ,512) with head offset
    float r0 = 1.0f / lrow0, r1 = 1.0f / lrow1;
    int row0 = i0 + warp * 16 + g;
    int row1 = row0 + 8;
    float* o0 = g_O + ((size_t)(b * 1024 + row0)) * 512 + h * 64;
    float* o1 = g_O + ((size_t)(b * 1024 + row1)) * 512 + h * 64;
    #pragma unroll
    for (int n = 0; n < 8; n++) {
        int d = n * 8 + 2 * t;
        o0[d    ] = oacc[n][0] * r0 + qbase[(g    ) * 64 + d    ];
        o0[d + 1] = oacc[n][1] * r0 + qbase[(g    ) * 64 + d + 1];
        o1[d    ] = oacc[n][2] * r1 + qbase[(g + 8) * 64 + d    ];
        o1[d + 1] = oacc[n][3] * r1 + qbase[(g + 8) * 64 + d + 1];
    }
}

// ---------------- LayerNorm over rows of 512 -------------------------------
__global__ void ln_kernel(const float* __restrict__ gg, const float* __restrict__ bb,
                          float* __restrict__ extout, int sel)
{
    __shared__ float red[4];
    const float* in = (sel == 0) ? g_O : g_U;
    float* out = (sel == 0) ? g_X : extout;
    const int row = blockIdx.x, t = threadIdx.x;
    const float* p = in + (size_t)row * 512;
    float v[4];
    #pragma unroll
    for (int i = 0; i < 4; i++) v[i] = p[t + 128 * i];

    float s = v[0] + v[1] + v[2] + v[3];
    s = warpSum(s);
    if ((t & 31) == 0) red[t >> 5] = s;
    __syncthreads();
    s = red[0] + red[1] + red[2] + red[3];
    float mean = s * (1.f / 512.f);
    __syncthreads();

    float ss = 0.f;
    #pragma unroll
    for (int i = 0; i < 4; i++) { float d = v[i] - mean; ss += d * d; }
    ss = warpSum(ss);
    if ((t & 31) == 0) red[t >> 5] = ss;
    __syncthreads();
    ss = red[0] + red[1] + red[2] + red[3];
    float inv = rsqrtf(ss * (1.f / 512.f) + 1e-5f);

    #pragma unroll
    for (int i = 0; i < 4; i++) {
        int c = t + 128 * i;
        out[(size_t)row * 512 + c] = (v[i] - mean) * inv * gg[c] + bb[c];
    }
}

// ---------------- output MLP: U = X + relu(X@Wo + bo) ----------------------
__global__ void gemm_out(const float* __restrict__ W, const float* __restrict__ bias)
{
    __shared__ float AsT[16][64];
    __shared__ float Bs[16][64];
    const int n0 = blockIdx.x * 64;
    const int m0 = blockIdx.y * 64;
    const int tid = threadIdx.x;
    const int tx = tid & 15, ty = tid >> 4;
    float acc[4][4] = {};

    for (int k0 = 0; k0 < 512; k0 += 16) {
        int r = tid >> 2, c4 = (tid & 3) << 2;
        float4 a = *(const float4*)(g_X + (size_t)(m0 + r) * 512 + k0 + c4);
        AsT[c4 + 0][r] = a.x; AsT[c4 + 1][r] = a.y;
        AsT[c4 + 2][r] = a.z; AsT[c4 + 3][r] = a.w;
        int br = tid >> 4, bc = (tid & 15) << 2;
        *(float4*)&Bs[br][bc] = *(const float4*)(W + (size_t)(k0 + br) * 512 + n0 + bc);
        __syncthreads();
        #pragma unroll
        for (int k = 0; k < 16; k++) {
            float af[4], bf[4];
            *(float4*)af = *(const float4*)&AsT[k][ty * 4];
            *(float4*)bf = *(const float4*)&Bs[k][tx * 4];
            #pragma unroll
            for (int i = 0; i < 4; i++)
                #pragma unroll
                for (int j = 0; j < 4; j++) acc[i][j] += af[i] * bf[j];
        }
        __syncthreads();
    }

    #pragma unroll
    for (int i = 0; i < 4; i++) {
        int m = m0 + ty * 4 + i;
        #pragma unroll
        for (int j = 0; j < 4; j++) {
            int c = n0 + tx * 4 + j;
            float y = acc[i][j] + bias[c];
            float xv = g_X[(size_t)m * 512 + c];
            g_U[(size_t)m * 512 + c] = xv + fmaxf(y, 0.f);
        }
    }
}

// ---------------- launch ----------------------------------------------------
extern "C" void kernel_launch(void* const* d_in, const int* in_sizes, int n_in,
                              void* d_out, int out_size)
{
    const float* Q    = (const float*)d_in[0];
    const float* K    = (const float*)d_in[1];
    const int*   mask = (const int*)  d_in[2];
    const float* Wq   = (const float*)d_in[3];
    const float* bq   = (const float*)d_in[4];
    const float* Wk   = (const float*)d_in[5];
    const float* bk   = (const float*)d_in[6];
    const float* Wv   = (const float*)d_in[7];
    const float* bv   = (const float*)d_in[8];
    const float* Wo   = (const float*)d_in[9];
    const float* bo   = (const float*)d_in[10];
    const float* g0   = (const float*)d_in[11];
    const float* b0   = (const float*)d_in[12];
    const float* g1   = (const float*)d_in[13];
    const float* b1   = (const float*)d_in[14];
    float* out = (float*)d_out;

    dim3 gp(DIM / 64, MROWS / 64);          // (8, 128)
    gemm_proj<<<gp, 256>>>(Q, Wq, bq, 0);
    gemm_proj<<<gp, 256>>>(K, Wk, bk, 1);
    gemm_proj<<<gp, 256>>>(K, Wv, bv, 2);

    dim3 gf(NQ / 128, BH);                  // (8, 64)
    flash_attn<<<gf, 256>>>(mask);

    ln_kernel<<<MROWS, 128>>>(g0, b0, nullptr, 0);
    gemm_out<<<gp, 256>>>(Wo, bo);
    ln_kernel<<<MROWS, 128>>>(g1, b1, out, 1);
}

// round 4
// speedup vs baseline: 1.8193x; 1.2918x over previous
#include <cuda_runtime.h>
#include <math.h>

// Problem constants: B=8, NQ=NK=1024, D=512, H=8, dh=64
#define BATCH 8
#define NQ 1024
#define NK 1024
#define DIM 512
#define HEADS 8
#define DH 64
#define BH (BATCH*HEADS)          // 64
#define MROWS (BATCH*NQ)          // 8192

// ---------------- scratch (device globals; allocation-free) ----------------
__device__ float g_q[BH * NK * DH];            // (bh, n, d)  16 MB
__device__ float g_k[BH * NK * DH];
__device__ float g_v[BH * NK * DH];
__device__ float g_O[MROWS * DIM];             // attention out (B,NQ,512)
__device__ float g_X[MROWS * DIM];             // post-LN0
__device__ float g_U[MROWS * DIM];             // X + relu(X@Wo+bo)

// ---------------- helpers ----------------
__device__ __forceinline__ float warpSum(float v) {
    #pragma unroll
    for (int o = 16; o > 0; o >>= 1) v += __shfl_xor_sync(0xffffffffu, v, o);
    return v;
}

__device__ __forceinline__ unsigned f2tf(float x) {
    unsigned u;
    asm("cvt.rna.tf32.f32 %0, %1;" : "=r"(u) : "f"(x));
    return u;
}

__device__ __forceinline__ void mma_tf32(float c[4],
                                         unsigned a0, unsigned a1, unsigned a2, unsigned a3,
                                         unsigned b0, unsigned b1)
{
    asm volatile(
        "mma.sync.aligned.m16n8k8.row.col.f32.tf32.tf32.f32 "
        "{%0,%1,%2,%3}, {%4,%5,%6,%7}, {%8,%9}, {%0,%1,%2,%3};\n"
        : "+f"(c[0]), "+f"(c[1]), "+f"(c[2]), "+f"(c[3])
        : "r"(a0), "r"(a1), "r"(a2), "r"(a3), "r"(b0), "r"(b1));
}

// ---------------- tensor-core GEMM: C = A(M,512) @ W(512,512) + bias -------
// mode 0/1/2: A = param, write g_q/g_k/g_v in head layout [(b*H+h)*1024+n][d]
// mode 3:     A = g_X (device symbol, param ignored), g_U = g_X + relu(C+bias)
// CTA: 256 thr (8 warps, 4m x 2n), tile 128(M) x 64(N), k-step 16.
__global__ void __launch_bounds__(256) gemm_tc(const float* __restrict__ Ain,
                                               const float* __restrict__ W,
                                               const float* __restrict__ bias,
                                               int mode)
{
    __shared__ unsigned AsT[16][136];   // [k][m] transposed A tile
    __shared__ unsigned Bs[16][72];     // [k][n] W tile
    const float* A = (mode == 3) ? (const float*)g_X : Ain;   // device-side symbol
    const int n0 = blockIdx.x * 64;
    const int m0 = blockIdx.y * 128;
    const int tid = threadIdx.x;
    const int warp = tid >> 5, lane = tid & 31;
    const int wm = warp >> 1, wn = warp & 1;
    const int g = lane >> 2, t = lane & 3;
    const int mbase = wm * 32;
    const int nbase = wn * 32;

    float acc[2][4][4];
    #pragma unroll
    for (int i = 0; i < 2; i++)
        #pragma unroll
        for (int j = 0; j < 4; j++)
            #pragma unroll
            for (int q = 0; q < 4; q++) acc[i][j][q] = 0.f;

    for (int k0 = 0; k0 < 512; k0 += 16) {
        __syncthreads();
        #pragma unroll
        for (int it = 0; it < 2; it++) {
            int idx = tid + it * 256;
            int r = idx >> 2, c4 = (idx & 3) << 2;
            float4 a = *(const float4*)(A + (size_t)(m0 + r) * 512 + k0 + c4);
            AsT[c4 + 0][r] = f2tf(a.x); AsT[c4 + 1][r] = f2tf(a.y);
            AsT[c4 + 2][r] = f2tf(a.z); AsT[c4 + 3][r] = f2tf(a.w);
        }
        {
            int r = tid >> 4, c4 = (tid & 15) << 2;
            float4 w = *(const float4*)(W + (size_t)(k0 + r) * 512 + n0 + c4);
            Bs[r][c4 + 0] = f2tf(w.x); Bs[r][c4 + 1] = f2tf(w.y);
            Bs[r][c4 + 2] = f2tf(w.z); Bs[r][c4 + 3] = f2tf(w.w);
        }
        __syncthreads();

        #pragma unroll
        for (int ks = 0; ks < 2; ks++) {
            int kk = ks * 8;
            unsigned av[2][4], bv[4][2];
            #pragma unroll
            for (int i = 0; i < 2; i++) {
                av[i][0] = AsT[kk + t    ][mbase + i * 16 + g    ];
                av[i][1] = AsT[kk + t    ][mbase + i * 16 + g + 8];
                av[i][2] = AsT[kk + t + 4][mbase + i * 16 + g    ];
                av[i][3] = AsT[kk + t + 4][mbase + i * 16 + g + 8];
            }
            #pragma unroll
            for (int j = 0; j < 4; j++) {
                bv[j][0] = Bs[kk + t    ][nbase + j * 8 + g];
                bv[j][1] = Bs[kk + t + 4][nbase + j * 8 + g];
            }
            #pragma unroll
            for (int i = 0; i < 2; i++)
                #pragma unroll
                for (int j = 0; j < 4; j++)
                    mma_tf32(acc[i][j], av[i][0], av[i][1], av[i][2], av[i][3],
                             bv[j][0], bv[j][1]);
        }
    }

    float* outp = (mode == 0) ? g_q : (mode == 1) ? g_k : (mode == 2) ? g_v : g_U;
    #pragma unroll
    for (int i = 0; i < 2; i++) {
        int r0 = m0 + mbase + i * 16 + g;
        #pragma unroll
        for (int j = 0; j < 4; j++) {
            int c0 = n0 + nbase + j * 8 + 2 * t;
            #pragma unroll
            for (int q = 0; q < 4; q++) {
                int r = r0 + (q >> 1) * 8;
                int c = c0 + (q & 1);
                float val = acc[i][j][q] + bias[c];
                if (mode < 3) {
                    int b = r >> 10, n = r & 1023;
                    int h = c >> 6, d = c & 63;
                    outp[(((size_t)(b * HEADS + h)) * 1024 + n) * 64 + d] = val;
                } else {
                    float xv = g_X[(size_t)r * 512 + c];
                    outp[(size_t)r * 512 + c] = xv + fmaxf(val, 0.f);
                }
            }
        }
    }
}

// ---------------- fused flash attention ------------------------------------
__global__ void __launch_bounds__(256) flash_attn(const int* __restrict__ mask)
{
    __shared__ unsigned KsT[64][33];       // K^T chunk: [d][n]
    __shared__ unsigned Vs[32][65];        // V chunk:   [kk][d]
    __shared__ unsigned Ps[8][16][33];     // per-warp P tile (16x32)
    __shared__ int ms[32];

    const int bh = blockIdx.y;
    const int b = bh >> 3, h = bh & 7;
    const int i0 = blockIdx.x * 128;
    const int tid = threadIdx.x;
    const int warp = tid >> 5, lane = tid & 31;
    const int g = lane >> 2, t = lane & 3;

    const float* qbase = g_q + ((size_t)bh * 1024 + i0 + warp * 16) * 64;
    unsigned qa[8][4];
    #pragma unroll
    for (int k = 0; k < 8; k++) {
        qa[k][0] = f2tf(qbase[(g    ) * 64 + k * 8 + t    ]);
        qa[k][1] = f2tf(qbase[(g + 8) * 64 + k * 8 + t    ]);
        qa[k][2] = f2tf(qbase[(g    ) * 64 + k * 8 + t + 4]);
        qa[k][3] = f2tf(qbase[(g + 8) * 64 + k * 8 + t + 4]);
    }

    float oacc[8][4];
    #pragma unroll
    for (int n = 0; n < 8; n++)
        #pragma unroll
        for (int j = 0; j < 4; j++) oacc[n][j] = 0.f;
    float mrow0 = -1e30f, mrow1 = -1e30f;
    float lrow0 = 0.f,    lrow1 = 0.f;

    const float* kbase = g_k + (size_t)bh * 1024 * 64;
    const float* vbase = g_v + (size_t)bh * 1024 * 64;
    const float scale = 0.044194173824159216f; // 1/sqrt(512)

    for (int j0 = 0; j0 < 1024; j0 += 32) {
        __syncthreads();
        {
            int r = tid >> 3;
            int c = (tid & 7) * 8;
            const float4* kp = (const float4*)(kbase + (size_t)(j0 + r) * 64 + c);
            const float4* vp = (const float4*)(vbase + (size_t)(j0 + r) * 64 + c);
            float4 k0 = kp[0], k1 = kp[1];
            float4 v0 = vp[0], v1 = vp[1];
            KsT[c + 0][r] = f2tf(k0.x); KsT[c + 1][r] = f2tf(k0.y);
            KsT[c + 2][r] = f2tf(k0.z); KsT[c + 3][r] = f2tf(k0.w);
            KsT[c + 4][r] = f2tf(k1.x); KsT[c + 5][r] = f2tf(k1.y);
            KsT[c + 6][r] = f2tf(k1.z); KsT[c + 7][r] = f2tf(k1.w);
            Vs[r][c + 0] = f2tf(v0.x); Vs[r][c + 1] = f2tf(v0.y);
            Vs[r][c + 2] = f2tf(v0.z); Vs[r][c + 3] = f2tf(v0.w);
            Vs[r][c + 4] = f2tf(v1.x); Vs[r][c + 5] = f2tf(v1.y);
            Vs[r][c + 6] = f2tf(v1.z); Vs[r][c + 7] = f2tf(v1.w);
        }
        if (tid < 32) ms[tid] = mask[b * 1024 + j0 + tid];
        __syncthreads();

        float sc[4][4];
        #pragma unroll
        for (int n = 0; n < 4; n++)
            #pragma unroll
            for (int j = 0; j < 4; j++) sc[n][j] = 0.f;
        #pragma unroll
        for (int k = 0; k < 8; k++) {
            #pragma unroll
            for (int n = 0; n < 4; n++) {
                unsigned b0 = KsT[k * 8 + t    ][n * 8 + g];
                unsigned b1 = KsT[k * 8 + t + 4][n * 8 + g];
                mma_tf32(sc[n], qa[k][0], qa[k][1], qa[k][2], qa[k][3], b0, b1);
            }
        }

        float mx0 = -1e30f, mx1 = -1e30f;
        #pragma unroll
        for (int n = 0; n < 4; n++) {
            int j = n * 8 + 2 * t;
            float v0 = ms[j]     ? sc[n][0] * scale : -10000.0f;
            float v1 = ms[j + 1] ? sc[n][1] * scale : -10000.0f;
            float v2 = ms[j]     ? sc[n][2] * scale : -10000.0f;
            float v3 = ms[j + 1] ? sc[n][3] * scale : -10000.0f;
            sc[n][0] = v0; sc[n][1] = v1; sc[n][2] = v2; sc[n][3] = v3;
            mx0 = fmaxf(mx0, fmaxf(v0, v1));
            mx1 = fmaxf(mx1, fmaxf(v2, v3));
        }
        mx0 = fmaxf(mx0, __shfl_xor_sync(0xffffffffu, mx0, 1));
        mx0 = fmaxf(mx0, __shfl_xor_sync(0xffffffffu, mx0, 2));
        mx1 = fmaxf(mx1, __shfl_xor_sync(0xffffffffu, mx1, 1));
        mx1 = fmaxf(mx1, __shfl_xor_sync(0xffffffffu, mx1, 2));

        float mn0 = fmaxf(mrow0, mx0), mn1 = fmaxf(mrow1, mx1);
        float f0 = __expf(mrow0 - mn0), f1 = __expf(mrow1 - mn1);
        float s0 = 0.f, s1 = 0.f;
        #pragma unroll
        for (int n = 0; n < 4; n++) {
            float p0 = __expf(sc[n][0] - mn0);
            float p1 = __expf(sc[n][1] - mn0);
            float p2 = __expf(sc[n][2] - mn1);
            float p3 = __expf(sc[n][3] - mn1);
            s0 += p0 + p1; s1 += p2 + p3;
            Ps[warp][g    ][n * 8 + 2 * t    ] = f2tf(p0);
            Ps[warp][g    ][n * 8 + 2 * t + 1] = f2tf(p1);
            Ps[warp][g + 8][n * 8 + 2 * t    ] = f2tf(p2);
            Ps[warp][g + 8][n * 8 + 2 * t + 1] = f2tf(p3);
        }
        s0 += __shfl_xor_sync(0xffffffffu, s0, 1);
        s0 += __shfl_xor_sync(0xffffffffu, s0, 2);
        s1 += __shfl_xor_sync(0xffffffffu, s1, 1);
        s1 += __shfl_xor_sync(0xffffffffu, s1, 2);

        lrow0 = lrow0 * f0 + s0;
        lrow1 = lrow1 * f1 + s1;
        mrow0 = mn0; mrow1 = mn1;
        #pragma unroll
        for (int n = 0; n < 8; n++) {
            oacc[n][0] *= f0; oacc[n][1] *= f0;
            oacc[n][2] *= f1; oacc[n][3] *= f1;
        }
        __syncwarp();

        #pragma unroll
        for (int k = 0; k < 4; k++) {
            unsigned a0 = Ps[warp][g    ][k * 8 + t    ];
            unsigned a1 = Ps[warp][g + 8][k * 8 + t    ];
            unsigned a2 = Ps[warp][g    ][k * 8 + t + 4];
            unsigned a3 = Ps[warp][g + 8][k * 8 + t + 4];
            #pragma unroll
            for (int n = 0; n < 8; n++) {
                unsigned b0 = Vs[k * 8 + t    ][n * 8 + g];
                unsigned b1 = Vs[k * 8 + t + 4][n * 8 + g];
                mma_tf32(oacc[n], a0, a1, a2, a3, b0, b1);
            }
        }
        __syncwarp();
    }

    float r0 = 1.0f / lrow0, r1 = 1.0f / lrow1;
    int row0 = i0 + warp * 16 + g;
    int row1 = row0 + 8;
    float* o0 = g_O + ((size_t)(b * 1024 + row0)) * 512 + h * 64;
    float* o1 = g_O + ((size_t)(b * 1024 + row1)) * 512 + h * 64;
    #pragma unroll
    for (int n = 0; n < 8; n++) {
        int d = n * 8 + 2 * t;
        o0[d    ] = oacc[n][0] * r0 + qbase[(g    ) * 64 + d    ];
        o0[d + 1] = oacc[n][1] * r0 + qbase[(g    ) * 64 + d + 1];
        o1[d    ] = oacc[n][2] * r1 + qbase[(g + 8) * 64 + d    ];
        o1[d + 1] = oacc[n][3] * r1 + qbase[(g + 8) * 64 + d + 1];
    }
}

// ---------------- LayerNorm over rows of 512 -------------------------------
__global__ void ln_kernel(const float* __restrict__ gg, const float* __restrict__ bb,
                          float* __restrict__ extout, int sel)
{
    __shared__ float red[4];
    const float* in = (sel == 0) ? g_O : g_U;
    float* out = (sel == 0) ? g_X : extout;
    const int row = blockIdx.x, t = threadIdx.x;
    const float* p = in + (size_t)row * 512;
    float v[4];
    #pragma unroll
    for (int i = 0; i < 4; i++) v[i] = p[t + 128 * i];

    float s = v[0] + v[1] + v[2] + v[3];
    s = warpSum(s);
    if ((t & 31) == 0) red[t >> 5] = s;
    __syncthreads();
    s = red[0] + red[1] + red[2] + red[3];
    float mean = s * (1.f / 512.f);
    __syncthreads();

    float ss = 0.f;
    #pragma unroll
    for (int i = 0; i < 4; i++) { float d = v[i] - mean; ss += d * d; }
    ss = warpSum(ss);
    if ((t & 31) == 0) red[t >> 5] = ss;
    __syncthreads();
    ss = red[0] + red[1] + red[2] + red[3];
    float inv = rsqrtf(ss * (1.f / 512.f) + 1e-5f);

    #pragma unroll
    for (int i = 0; i < 4; i++) {
        int c = t + 128 * i;
        out[(size_t)row * 512 + c] = (v[i] - mean) * inv * gg[c] + bb[c];
    }
}

// ---------------- launch ----------------------------------------------------
extern "C" void kernel_launch(void* const* d_in, const int* in_sizes, int n_in,
                              void* d_out, int out_size)
{
    const float* Q    = (const float*)d_in[0];
    const float* K    = (const float*)d_in[1];
    const int*   mask = (const int*)  d_in[2];
    const float* Wq   = (const float*)d_in[3];
    const float* bq   = (const float*)d_in[4];
    const float* Wk   = (const float*)d_in[5];
    const float* bk   = (const float*)d_in[6];
    const float* Wv   = (const float*)d_in[7];
    const float* bv   = (const float*)d_in[8];
    const float* Wo   = (const float*)d_in[9];
    const float* bo   = (const float*)d_in[10];
    const float* g0   = (const float*)d_in[11];
    const float* b0   = (const float*)d_in[12];
    const float* g1   = (const float*)d_in[13];
    const float* b1   = (const float*)d_in[14];
    float* out = (float*)d_out;

    dim3 gp(DIM / 64, MROWS / 128);         // (8, 64)
    gemm_tc<<<gp, 256>>>(Q, Wq, bq, 0);
    gemm_tc<<<gp, 256>>>(K, Wk, bk, 1);
    gemm_tc<<<gp, 256>>>(K, Wv, bv, 2);

    dim3 gf(NQ / 128, BH);                  // (8, 64)
    flash_attn<<<gf, 256>>>(mask);

    ln_kernel<<<MROWS, 128>>>(g0, b0, nullptr, 0);
    gemm_tc<<<gp, 256>>>(Q /*ignored*/, Wo, bo, 3);
    ln_kernel<<<MROWS, 128>>>(g1, b1, out, 1);
}

// round 5
// speedup vs baseline: 2.9448x; 1.6186x over previous
#include <cuda_runtime.h>
#include <math.h>

// Problem constants: B=8, NQ=NK=1024, D=512, H=8, dh=64
#define BATCH 8
#define NQ 1024
#define NK 1024
#define DIM 512
#define HEADS 8
#define DH 64
#define BH (BATCH*HEADS)          // 64
#define MROWS (BATCH*NQ)          // 8192

// ---------------- scratch (device globals; allocation-free) ----------------
__device__ float g_q[BH * NK * DH];
__device__ float g_k[BH * NK * DH];
__device__ float g_v[BH * NK * DH];
__device__ float g_O[MROWS * DIM];
__device__ float g_X[MROWS * DIM];
__device__ float g_U[MROWS * DIM];
__device__ int   g_idx[BATCH * NK];   // compacted unmasked key indices
__device__ int   g_cnt[BATCH];        // count of unmasked keys per batch

// ---------------- helpers ----------------
__device__ __forceinline__ float warpSum(float v) {
    #pragma unroll
    for (int o = 16; o > 0; o >>= 1) v += __shfl_xor_sync(0xffffffffu, v, o);
    return v;
}

__device__ __forceinline__ unsigned f2tf(float x) {
    unsigned u;
    asm("cvt.rna.tf32.f32 %0, %1;" : "=r"(u) : "f"(x));
    return u;
}

__device__ __forceinline__ void mma_tf32(float c[4],
                                         unsigned a0, unsigned a1, unsigned a2, unsigned a3,
                                         unsigned b0, unsigned b1)
{
    asm volatile(
        "mma.sync.aligned.m16n8k8.row.col.f32.tf32.tf32.f32 "
        "{%0,%1,%2,%3}, {%4,%5,%6,%7}, {%8,%9}, {%0,%1,%2,%3};\n"
        : "+f"(c[0]), "+f"(c[1]), "+f"(c[2]), "+f"(c[3])
        : "r"(a0), "r"(a1), "r"(a2), "r"(a3), "r"(b0), "r"(b1));
}

// ---------------- mask compaction: per batch, indices where mask!=0 --------
__global__ void compact_mask(const int* __restrict__ mask)
{
    __shared__ int warpsums[32];
    const int b = blockIdx.x, t = threadIdx.x;
    const int lane = t & 31, warp = t >> 5;
    int m = (mask[b * 1024 + t] != 0) ? 1 : 0;
    unsigned bal = __ballot_sync(0xffffffffu, m);
    int pre = __popc(bal & ((1u << lane) - 1u));
    if (lane == 0) warpsums[warp] = __popc(bal);
    __syncthreads();
    if (warp == 0) {
        int v = warpsums[lane];
        #pragma unroll
        for (int o = 1; o < 32; o <<= 1) {
            int u = __shfl_up_sync(0xffffffffu, v, o);
            if (lane >= o) v += u;
        }
        warpsums[lane] = v;   // inclusive scan
    }
    __syncthreads();
    int base = (warp == 0) ? 0 : warpsums[warp - 1];
    if (m) g_idx[b * 1024 + base + pre] = t;
    if (t == 1023) g_cnt[b] = warpsums[31];
}

// ---------------- tensor-core GEMM (double-buffered) -----------------------
// mode 0/1/2: A = param, write g_q/g_k/g_v in head layout
// mode 3:     A = g_X (symbol), g_U = g_X + relu(C + bias)
__global__ void __launch_bounds__(256) gemm_tc(const float* __restrict__ Ain,
                                               const float* __restrict__ W,
                                               const float* __restrict__ bias,
                                               int mode)
{
    __shared__ unsigned AsT[2][16][136];
    __shared__ unsigned Bs[2][16][72];
    const float* A = (mode == 3) ? (const float*)g_X : Ain;
    const int n0 = blockIdx.x * 64;
    const int m0 = blockIdx.y * 128;
    const int tid = threadIdx.x;
    const int warp = tid >> 5, lane = tid & 31;
    const int wm = warp >> 1, wn = warp & 1;
    const int g = lane >> 2, t = lane & 3;
    const int mbase = wm * 32;
    const int nbase = wn * 32;

    auto loadAB = [&](int k0, int bufi) {
        #pragma unroll
        for (int it = 0; it < 2; it++) {
            int idx = tid + it * 256;
            int r = idx >> 2, c4 = (idx & 3) << 2;
            float4 a = *(const float4*)(A + (size_t)(m0 + r) * 512 + k0 + c4);
            AsT[bufi][c4 + 0][r] = f2tf(a.x); AsT[bufi][c4 + 1][r] = f2tf(a.y);
            AsT[bufi][c4 + 2][r] = f2tf(a.z); AsT[bufi][c4 + 3][r] = f2tf(a.w);
        }
        int r = tid >> 4, c4 = (tid & 15) << 2;
        float4 w = *(const float4*)(W + (size_t)(k0 + r) * 512 + n0 + c4);
        Bs[bufi][r][c4 + 0] = f2tf(w.x); Bs[bufi][r][c4 + 1] = f2tf(w.y);
        Bs[bufi][r][c4 + 2] = f2tf(w.z); Bs[bufi][r][c4 + 3] = f2tf(w.w);
    };

    float acc[2][4][4];
    #pragma unroll
    for (int i = 0; i < 2; i++)
        #pragma unroll
        for (int j = 0; j < 4; j++)
            #pragma unroll
            for (int q = 0; q < 4; q++) acc[i][j][q] = 0.f;

    loadAB(0, 0);
    __syncthreads();

    for (int it = 0; it < 32; it++) {
        int cur = it & 1;
        if (it < 31) loadAB((it + 1) * 16, cur ^ 1);
        #pragma unroll
        for (int ks = 0; ks < 2; ks++) {
            int kk = ks * 8;
            unsigned av[2][4], bv[4][2];
            #pragma unroll
            for (int i = 0; i < 2; i++) {
                av[i][0] = AsT[cur][kk + t    ][mbase + i * 16 + g    ];
                av[i][1] = AsT[cur][kk + t    ][mbase + i * 16 + g + 8];
                av[i][2] = AsT[cur][kk + t + 4][mbase + i * 16 + g    ];
                av[i][3] = AsT[cur][kk + t + 4][mbase + i * 16 + g + 8];
            }
            #pragma unroll
            for (int j = 0; j < 4; j++) {
                bv[j][0] = Bs[cur][kk + t    ][nbase + j * 8 + g];
                bv[j][1] = Bs[cur][kk + t + 4][nbase + j * 8 + g];
            }
            #pragma unroll
            for (int i = 0; i < 2; i++)
                #pragma unroll
                for (int j = 0; j < 4; j++)
                    mma_tf32(acc[i][j], av[i][0], av[i][1], av[i][2], av[i][3],
                             bv[j][0], bv[j][1]);
        }
        __syncthreads();
    }

    float* outp = (mode == 0) ? g_q : (mode == 1) ? g_k : (mode == 2) ? g_v : g_U;
    #pragma unroll
    for (int i = 0; i < 2; i++) {
        int r0 = m0 + mbase + i * 16 + g;
        #pragma unroll
        for (int j = 0; j < 4; j++) {
            int c0 = n0 + nbase + j * 8 + 2 * t;
            #pragma unroll
            for (int q = 0; q < 4; q++) {
                int r = r0 + (q >> 1) * 8;
                int c = c0 + (q & 1);
                float val = acc[i][j][q] + bias[c];
                if (mode < 3) {
                    int b = r >> 10, n = r & 1023;
                    int h = c >> 6, d = c & 63;
                    outp[(((size_t)(b * HEADS + h)) * 1024 + n) * 64 + d] = val;
                } else {
                    float xv = g_X[(size_t)r * 512 + c];
                    outp[(size_t)r * 512 + c] = xv + fmaxf(val, 0.f);
                }
            }
        }
    }
}

// ---------------- fused flash attention (compacted keys, DB, CF layouts) ---
// dyn smem: Ks [2][64][40] ([d][key] tf32), Vs [2][64][40] ([d][key]),
//           Ps [8][32][24] (PsT[col][row] per warp)
#define KS_OFF 0
#define VS_OFF (2*64*40)
#define PS_OFF (4*64*40)
#define SMEM_FLASH ((4*64*40 + 8*32*24) * 4)

__global__ void __launch_bounds__(256) flash_attn()
{
    extern __shared__ unsigned sm[];
    unsigned* Ksm = sm + KS_OFF;
    unsigned* Vsm = sm + VS_OFF;
    unsigned* Psm = sm + PS_OFF;

    const int bh = blockIdx.y;
    const int b = bh >> 3, h = bh & 7;
    const int i0 = blockIdx.x * 128;
    const int tid = threadIdx.x;
    const int warp = tid >> 5, lane = tid & 31;
    const int g = lane >> 2, t = lane & 3;

    const int nk = g_cnt[b];
    const int nchunks = (nk + 31) >> 5;
    const int* idxp = g_idx + b * 1024;
    const float* kbase = g_k + (size_t)bh * 1024 * 64;
    const float* vbase = g_v + (size_t)bh * 1024 * 64;
    const float scale = 0.044194173824159216f; // 1/sqrt(512)

    // Q fragments, pre-scaled (single rounding: cvt(q*scale))
    const float* qbase = g_q + ((size_t)bh * 1024 + i0 + warp * 16) * 64;
    unsigned qa[8][4];
    #pragma unroll
    for (int k = 0; k < 8; k++) {
        qa[k][0] = f2tf(qbase[(g    ) * 64 + k * 8 + t    ] * scale);
        qa[k][1] = f2tf(qbase[(g + 8) * 64 + k * 8 + t    ] * scale);
        qa[k][2] = f2tf(qbase[(g    ) * 64 + k * 8 + t + 4] * scale);
        qa[k][3] = f2tf(qbase[(g + 8) * 64 + k * 8 + t + 4] * scale);
    }

    // chunk loader: key r of chunk -> transposed [d][key] stores, stride 40
    auto load_chunk = [&](int ch) {
        int bufi = ch & 1;
        unsigned* Kb = Ksm + bufi * 2560;
        unsigned* Vb = Vsm + bufi * 2560;
        int r = tid >> 3;
        int c = (tid & 7) * 8;
        int key = ch * 32 + r;
        if (key < nk) {
            int kidx = idxp[key];
            const float4* kp = (const float4*)(kbase + (size_t)kidx * 64 + c);
            const float4* vp = (const float4*)(vbase + (size_t)kidx * 64 + c);
            float4 k0 = kp[0], k1 = kp[1];
            float4 v0 = vp[0], v1 = vp[1];
            Kb[(c + 0) * 40 + r] = f2tf(k0.x); Kb[(c + 1) * 40 + r] = f2tf(k0.y);
            Kb[(c + 2) * 40 + r] = f2tf(k0.z); Kb[(c + 3) * 40 + r] = f2tf(k0.w);
            Kb[(c + 4) * 40 + r] = f2tf(k1.x); Kb[(c + 5) * 40 + r] = f2tf(k1.y);
            Kb[(c + 6) * 40 + r] = f2tf(k1.z); Kb[(c + 7) * 40 + r] = f2tf(k1.w);
            Vb[(c + 0) * 40 + r] = f2tf(v0.x); Vb[(c + 1) * 40 + r] = f2tf(v0.y);
            Vb[(c + 2) * 40 + r] = f2tf(v0.z); Vb[(c + 3) * 40 + r] = f2tf(v0.w);
            Vb[(c + 4) * 40 + r] = f2tf(v1.x); Vb[(c + 5) * 40 + r] = f2tf(v1.y);
            Vb[(c + 6) * 40 + r] = f2tf(v1.z); Vb[(c + 7) * 40 + r] = f2tf(v1.w);
        } else {
            #pragma unroll
            for (int q = 0; q < 8; q++) {
                Kb[(c + q) * 40 + r] = 0u;
                Vb[(c + q) * 40 + r] = 0u;
            }
        }
    };

    float oacc[8][4];
    #pragma unroll
    for (int n = 0; n < 8; n++)
        #pragma unroll
        for (int j = 0; j < 4; j++) oacc[n][j] = 0.f;
    float mrow0 = -1e30f, mrow1 = -1e30f;
    float lrow0 = 0.f,    lrow1 = 0.f;

    unsigned* Pw = Psm + warp * 768;   // PsT[32][24]

    load_chunk(0);
    __syncthreads();

    for (int ch = 0; ch < nchunks; ch++) {
        const int cur = ch & 1;
        if (ch + 1 < nchunks) load_chunk(ch + 1);
        const unsigned* Kb = Ksm + cur * 2560;
        const unsigned* Vb = Vsm + cur * 2560;
        const int j0 = ch * 32;

        // S = (Q*scale) @ K^T  (16 rows x 32 chunk keys)
        float sc[4][4];
        #pragma unroll
        for (int n = 0; n < 4; n++)
            #pragma unroll
            for (int j = 0; j < 4; j++) sc[n][j] = 0.f;
        #pragma unroll
        for (int k = 0; k < 8; k++) {
            #pragma unroll
            for (int n = 0; n < 4; n++) {
                unsigned b0 = Kb[(k * 8 + t    ) * 40 + n * 8 + g];
                unsigned b1 = Kb[(k * 8 + t + 4) * 40 + n * 8 + g];
                mma_tf32(sc[n], qa[k][0], qa[k][1], qa[k][2], qa[k][3], b0, b1);
            }
        }

        // tail predication (cols >= nk -> -10000), online softmax
        float mx0 = -1e30f, mx1 = -1e30f;
        #pragma unroll
        for (int n = 0; n < 4; n++) {
            int c0 = j0 + n * 8 + 2 * t;
            bool ok0 = c0 < nk, ok1 = (c0 + 1) < nk;
            float v0 = ok0 ? sc[n][0] : -10000.0f;
            float v1 = ok1 ? sc[n][1] : -10000.0f;
            float v2 = ok0 ? sc[n][2] : -10000.0f;
            float v3 = ok1 ? sc[n][3] : -10000.0f;
            sc[n][0] = v0; sc[n][1] = v1; sc[n][2] = v2; sc[n][3] = v3;
            mx0 = fmaxf(mx0, fmaxf(v0, v1));
            mx1 = fmaxf(mx1, fmaxf(v2, v3));
        }
        mx0 = fmaxf(mx0, __shfl_xor_sync(0xffffffffu, mx0, 1));
        mx0 = fmaxf(mx0, __shfl_xor_sync(0xffffffffu, mx0, 2));
        mx1 = fmaxf(mx1, __shfl_xor_sync(0xffffffffu, mx1, 1));
        mx1 = fmaxf(mx1, __shfl_xor_sync(0xffffffffu, mx1, 2));

        float mn0 = fmaxf(mrow0, mx0), mn1 = fmaxf(mrow1, mx1);
        float f0 = __expf(mrow0 - mn0), f1 = __expf(mrow1 - mn1);
        float s0 = 0.f, s1 = 0.f;
        #pragma unroll
        for (int n = 0; n < 4; n++) {
            float p0 = __expf(sc[n][0] - mn0);
            float p1 = __expf(sc[n][1] - mn0);
            float p2 = __expf(sc[n][2] - mn1);
            float p3 = __expf(sc[n][3] - mn1);
            s0 += p0 + p1; s1 += p2 + p3;
            Pw[(n * 8 + 2 * t    ) * 24 + g    ] = f2tf(p0);
            Pw[(n * 8 + 2 * t + 1) * 24 + g    ] = f2tf(p1);
            Pw[(n * 8 + 2 * t    ) * 24 + g + 8] = f2tf(p2);
            Pw[(n * 8 + 2 * t + 1) * 24 + g + 8] = f2tf(p3);
        }
        s0 += __shfl_xor_sync(0xffffffffu, s0, 1);
        s0 += __shfl_xor_sync(0xffffffffu, s0, 2);
        s1 += __shfl_xor_sync(0xffffffffu, s1, 1);
        s1 += __shfl_xor_sync(0xffffffffu, s1, 2);

        lrow0 = lrow0 * f0 + s0;
        lrow1 = lrow1 * f1 + s1;
        mrow0 = mn0; mrow1 = mn1;
        #pragma unroll
        for (int n = 0; n < 8; n++) {
            oacc[n][0] *= f0; oacc[n][1] *= f0;
            oacc[n][2] *= f1; oacc[n][3] *= f1;
        }
        __syncwarp();

        // O += P @ V
        #pragma unroll
        for (int k = 0; k < 4; k++) {
            unsigned a0 = Pw[(k * 8 + t    ) * 24 + g    ];
            unsigned a1 = Pw[(k * 8 + t    ) * 24 + g + 8];
            unsigned a2 = Pw[(k * 8 + t + 4) * 24 + g    ];
            unsigned a3 = Pw[(k * 8 + t + 4) * 24 + g + 8];
            #pragma unroll
            for (int n = 0; n < 8; n++) {
                unsigned b0 = Vb[(n * 8 + g) * 40 + k * 8 + t    ];
                unsigned b1 = Vb[(n * 8 + g) * 40 + k * 8 + t + 4];
                mma_tf32(oacc[n], a0, a1, a2, a3, b0, b1);
            }
        }
        __syncthreads();
    }

    float r0 = 1.0f / lrow0, r1 = 1.0f / lrow1;
    int row0 = i0 + warp * 16 + g;
    int row1 = row0 + 8;
    float* o0 = g_O + ((size_t)(b * 1024 + row0)) * 512 + h * 64;
    float* o1 = g_O + ((size_t)(b * 1024 + row1)) * 512 + h * 64;
    #pragma unroll
    for (int n = 0; n < 8; n++) {
        int d = n * 8 + 2 * t;
        o0[d    ] = oacc[n][0] * r0 + qbase[(g    ) * 64 + d    ];
        o0[d + 1] = oacc[n][1] * r0 + qbase[(g    ) * 64 + d + 1];
        o1[d    ] = oacc[n][2] * r1 + qbase[(g + 8) * 64 + d    ];
        o1[d + 1] = oacc[n][3] * r1 + qbase[(g + 8) * 64 + d + 1];
    }
}

// ---------------- LayerNorm over rows of 512 -------------------------------
__global__ void ln_kernel(const float* __restrict__ gg, const float* __restrict__ bb,
                          float* __restrict__ extout, int sel)
{
    __shared__ float red[4];
    const float* in = (sel == 0) ? g_O : g_U;
    float* out = (sel == 0) ? g_X : extout;
    const int row = blockIdx.x, t = threadIdx.x;
    const float* p = in + (size_t)row * 512;
    float v[4];
    #pragma unroll
    for (int i = 0; i < 4; i++) v[i] = p[t + 128 * i];

    float s = v[0] + v[1] + v[2] + v[3];
    s = warpSum(s);
    if ((t & 31) == 0) red[t >> 5] = s;
    __syncthreads();
    s = red[0] + red[1] + red[2] + red[3];
    float mean = s * (1.f / 512.f);
    __syncthreads();

    float ss = 0.f;
    #pragma unroll
    for (int i = 0; i < 4; i++) { float d = v[i] - mean; ss += d * d; }
    ss = warpSum(ss);
    if ((t & 31) == 0) red[t >> 5] = ss;
    __syncthreads();
    ss = red[0] + red[1] + red[2] + red[3];
    float inv = rsqrtf(ss * (1.f / 512.f) + 1e-5f);

    #pragma unroll
    for (int i = 0; i < 4; i++) {
        int c = t + 128 * i;
        out[(size_t)row * 512 + c] = (v[i] - mean) * inv * gg[c] + bb[c];
    }
}

// ---------------- launch ----------------------------------------------------
extern "C" void kernel_launch(void* const* d_in, const int* in_sizes, int n_in,
                              void* d_out, int out_size)
{
    const float* Q    = (const float*)d_in[0];
    const float* K    = (const float*)d_in[1];
    const int*   mask = (const int*)  d_in[2];
    const float* Wq   = (const float*)d_in[3];
    const float* bq   = (const float*)d_in[4];
    const float* Wk   = (const float*)d_in[5];
    const float* bk   = (const float*)d_in[6];
    const float* Wv   = (const float*)d_in[7];
    const float* bv   = (const float*)d_in[8];
    const float* Wo   = (const float*)d_in[9];
    const float* bo   = (const float*)d_in[10];
    const float* g0   = (const float*)d_in[11];
    const float* b0   = (const float*)d_in[12];
    const float* g1   = (const float*)d_in[13];
    const float* b1   = (const float*)d_in[14];
    float* out = (float*)d_out;

    static bool attr_set = false;
    if (!attr_set) {
        cudaFuncSetAttribute(flash_attn, cudaFuncAttributeMaxDynamicSharedMemorySize,
                             SMEM_FLASH);
        attr_set = true;
    }

    compact_mask<<<BATCH, 1024>>>(mask);

    dim3 gp(DIM / 64, MROWS / 128);         // (8, 64)
    gemm_tc<<<gp, 256>>>(Q, Wq, bq, 0);
    gemm_tc<<<gp, 256>>>(K, Wk, bk, 1);
    gemm_tc<<<gp, 256>>>(K, Wv, bv, 2);

    dim3 gf(NQ / 128, BH);                  // (8, 64)
    flash_attn<<<gf, 256, SMEM_FLASH>>>();

    ln_kernel<<<MROWS, 128>>>(g0, b0, nullptr, 0);
    gemm_tc<<<gp, 256>>>(Q /*ignored*/, Wo, bo, 3);
    ln_kernel<<<MROWS, 128>>>(g1, b1, out, 1);
}

// round 6
// speedup vs baseline: 4.3395x; 1.4736x over previous
#include <cuda_runtime.h>
#include <math.h>

// Problem constants: B=8, NQ=NK=1024, D=512, H=8, dh=64
#define BATCH 8
#define NQ 1024
#define NK 1024
#define DIM 512
#define HEADS 8
#define DH 64
#define BH (BATCH*HEADS)          // 64
#define MROWS (BATCH*NQ)          // 8192

// ---------------- scratch (device globals; allocation-free) ----------------
__device__ float g_q[BH * NK * DH];
__device__ float g_k[BH * NK * DH];
__device__ float g_v[BH * NK * DH];
__device__ float g_O[MROWS * DIM];
__device__ float g_X[MROWS * DIM];
__device__ float g_U[MROWS * DIM];
__device__ int   g_idx[BATCH * NK];
__device__ int   g_cnt[BATCH];

// ---------------- helpers ----------------
__device__ __forceinline__ float warpSum(float v) {
    #pragma unroll
    for (int o = 16; o > 0; o >>= 1) v += __shfl_xor_sync(0xffffffffu, v, o);
    return v;
}

__device__ __forceinline__ unsigned f2tf(float x) {
    unsigned u;
    asm("cvt.rna.tf32.f32 %0, %1;" : "=r"(u) : "f"(x));
    return u;
}

__device__ __forceinline__ void mma_tf32(float c[4],
                                         unsigned a0, unsigned a1, unsigned a2, unsigned a3,
                                         unsigned b0, unsigned b1)
{
    asm volatile(
        "mma.sync.aligned.m16n8k8.row.col.f32.tf32.tf32.f32 "
        "{%0,%1,%2,%3}, {%4,%5,%6,%7}, {%8,%9}, {%0,%1,%2,%3};\n"
        : "+f"(c[0]), "+f"(c[1]), "+f"(c[2]), "+f"(c[3])
        : "r"(a0), "r"(a1), "r"(a2), "r"(a3), "r"(b0), "r"(b1));
}

// ---------------- mask compaction ----------------
__global__ void compact_mask(const int* __restrict__ mask)
{
    __shared__ int warpsums[32];
    const int b = blockIdx.x, t = threadIdx.x;
    const int lane = t & 31, warp = t >> 5;
    int m = (mask[b * 1024 + t] != 0) ? 1 : 0;
    unsigned bal = __ballot_sync(0xffffffffu, m);
    int pre = __popc(bal & ((1u << lane) - 1u));
    if (lane == 0) warpsums[warp] = __popc(bal);
    __syncthreads();
    if (warp == 0) {
        int v = warpsums[lane];
        #pragma unroll
        for (int o = 1; o < 32; o <<= 1) {
            int u = __shfl_up_sync(0xffffffffu, v, o);
            if (lane >= o) v += u;
        }
        warpsums[lane] = v;
    }
    __syncthreads();
    int base = (warp == 0) ? 0 : warpsums[warp - 1];
    if (m) g_idx[b * 1024 + base + pre] = t;
    if (t == 1023) g_cnt[b] = warpsums[31];
}

// ---------------- 128x128 tensor-core GEMM ---------------------------------
// mode 0 (grid.z = 3): z=0: Q@Wq+bq -> g_q ; z=1: K@Wk+bk -> g_k ; z=2: K@Wv+bv -> g_v
//                      output in head layout [(b*H+h)*1024+n][d]
// mode 1 (grid.z = 1): g_U = g_X + relu(g_X@W0 + B0)
// 8 warps 2(m) x 4(n), warp tile 64x32, k-step 16, double buffered.
__global__ void __launch_bounds__(256, 2) gemm128(
    const float* __restrict__ AQ, const float* __restrict__ AK,
    const float* __restrict__ W0, const float* __restrict__ B0v,
    const float* __restrict__ W1, const float* __restrict__ B1v,
    const float* __restrict__ W2, const float* __restrict__ B2v,
    int mode)
{
    __shared__ unsigned AsT[2][16][136];   // [k][m^sw] transposed A tile
    __shared__ unsigned Bs[2][16][136];    // [k][n]
    const int z = blockIdx.z;
    const float* A; const float* W; const float* bias; float* outp;
    if (mode == 0) {
        A    = (z == 0) ? AQ : AK;
        W    = (z == 0) ? W0 : (z == 1) ? W1 : W2;
        bias = (z == 0) ? B0v : (z == 1) ? B1v : B2v;
        outp = (z == 0) ? g_q : (z == 1) ? g_k : g_v;
    } else {
        A = (const float*)g_X; W = W0; bias = B0v; outp = g_U;
    }
    const int n0 = blockIdx.x * 128;
    const int m0 = blockIdx.y * 128;
    const int tid = threadIdx.x;
    const int warp = tid >> 5, lane = tid & 31;
    const int wm = warp >> 2, wn = warp & 3;
    const int g = lane >> 2, t = lane & 3;
    const int mbase = wm * 64;
    const int nbase = wn * 32;

    auto loadAB = [&](int k0, int bufi) {
        #pragma unroll
        for (int it = 0; it < 2; it++) {
            int idx = tid + it * 256;
            int r = idx >> 2, c4 = (idx & 3) << 2;
            float4 a = *(const float4*)(A + (size_t)(m0 + r) * 512 + k0 + c4);
            int sw = (c4 >> 2) << 3;       // XOR swizzle: conflict-free transposed stores
            int rc = r ^ sw;
            AsT[bufi][c4 + 0][rc] = f2tf(a.x);
            AsT[bufi][c4 + 1][rc] = f2tf(a.y);
            AsT[bufi][c4 + 2][rc] = f2tf(a.z);
            AsT[bufi][c4 + 3][rc] = f2tf(a.w);
        }
        #pragma unroll
        for (int it = 0; it < 2; it++) {
            int idx = tid + it * 256;
            int r = idx >> 5, c4 = (idx & 31) << 2;
            float4 w = *(const float4*)(W + (size_t)(k0 + r) * 512 + n0 + c4);
            uint4 pw = make_uint4(f2tf(w.x), f2tf(w.y), f2tf(w.z), f2tf(w.w));
            *(uint4*)&Bs[bufi][r][c4] = pw;   // STS.128, conflict-free
        }
    };

    float acc[4][4][4];
    #pragma unroll
    for (int i = 0; i < 4; i++)
        #pragma unroll
        for (int j = 0; j < 4; j++)
            #pragma unroll
            for (int q = 0; q < 4; q++) acc[i][j][q] = 0.f;

    loadAB(0, 0);
    __syncthreads();

    for (int it = 0; it < 32; it++) {
        int cur = it & 1;
        if (it < 31) loadAB((it + 1) * 16, cur ^ 1);
        #pragma unroll
        for (int ks = 0; ks < 2; ks++) {
            int kk = ks * 8;
            int sw0 = (kk >> 2) << 3;            // rows kk..kk+3
            int sw1 = ((kk + 4) >> 2) << 3;      // rows kk+4..kk+7
            unsigned av[4][4], bv[4][2];
            #pragma unroll
            for (int i = 0; i < 4; i++) {
                int mb = mbase + i * 16;
                av[i][0] = AsT[cur][kk + t    ][(mb + g    ) ^ sw0];
                av[i][1] = AsT[cur][kk + t    ][(mb + g + 8) ^ sw0];
                av[i][2] = AsT[cur][kk + t + 4][(mb + g    ) ^ sw1];
                av[i][3] = AsT[cur][kk + t + 4][(mb + g + 8) ^ sw1];
            }
            #pragma unroll
            for (int j = 0; j < 4; j++) {
                bv[j][0] = Bs[cur][kk + t    ][nbase + j * 8 + g];
                bv[j][1] = Bs[cur][kk + t + 4][nbase + j * 8 + g];
            }
            #pragma unroll
            for (int i = 0; i < 4; i++)
                #pragma unroll
                for (int j = 0; j < 4; j++)
                    mma_tf32(acc[i][j], av[i][0], av[i][1], av[i][2], av[i][3],
                             bv[j][0], bv[j][1]);
        }
        __syncthreads();
    }

    #pragma unroll
    for (int i = 0; i < 4; i++) {
        int r0 = m0 + mbase + i * 16 + g;
        #pragma unroll
        for (int j = 0; j < 4; j++) {
            int c0 = n0 + nbase + j * 8 + 2 * t;
            #pragma unroll
            for (int q = 0; q < 4; q++) {
                int r = r0 + (q >> 1) * 8;
                int c = c0 + (q & 1);
                float val = acc[i][j][q] + bias[c];
                if (mode == 0) {
                    int b = r >> 10, n = r & 1023;
                    int h = c >> 6, d = c & 63;
                    outp[(((size_t)(b * HEADS + h)) * 1024 + n) * 64 + d] = val;
                } else {
                    float xv = g_X[(size_t)r * 512 + c];
                    outp[(size_t)r * 512 + c] = xv + fmaxf(val, 0.f);
                }
            }
        }
    }
}

// ---------------- fused flash attention (compacted keys, swizzled K/V) -----
// dyn smem: Ks [2][64][40] ([d][key^sw]), Vs [2][64][40], Ps [8][32][24]
#define KS_OFF 0
#define VS_OFF (2*64*40)
#define PS_OFF (4*64*40)
#define SMEM_FLASH ((4*64*40 + 8*32*24) * 4)

__global__ void __launch_bounds__(256) flash_attn()
{
    extern __shared__ unsigned sm[];
    unsigned* Ksm = sm + KS_OFF;
    unsigned* Vsm = sm + VS_OFF;
    unsigned* Psm = sm + PS_OFF;

    const int bh = blockIdx.y;
    const int b = bh >> 3, h = bh & 7;
    const int i0 = blockIdx.x * 128;
    const int tid = threadIdx.x;
    const int warp = tid >> 5, lane = tid & 31;
    const int g = lane >> 2, t = lane & 3;

    const int nk = g_cnt[b];
    const int nchunks = (nk + 31) >> 5;
    const int* idxp = g_idx + b * 1024;
    const float* kbase = g_k + (size_t)bh * 1024 * 64;
    const float* vbase = g_v + (size_t)bh * 1024 * 64;
    const float scale = 0.044194173824159216f; // 1/sqrt(512)

    const float* qbase = g_q + ((size_t)bh * 1024 + i0 + warp * 16) * 64;
    unsigned qa[8][4];
    #pragma unroll
    for (int k = 0; k < 8; k++) {
        qa[k][0] = f2tf(qbase[(g    ) * 64 + k * 8 + t    ] * scale);
        qa[k][1] = f2tf(qbase[(g + 8) * 64 + k * 8 + t    ] * scale);
        qa[k][2] = f2tf(qbase[(g    ) * 64 + k * 8 + t + 4] * scale);
        qa[k][3] = f2tf(qbase[(g + 8) * 64 + k * 8 + t + 4] * scale);
    }

    // store column swizzle: physical col = (key + 4*(d>>3)) & 31  (bijective per d-row)
    auto load_chunk = [&](int ch) {
        int bufi = ch & 1;
        unsigned* Kb = Ksm + bufi * 2560;
        unsigned* Vb = Vsm + bufi * 2560;
        int r = tid >> 3;              // key within chunk 0..31
        int c = (tid & 7) * 8;         // d base
        int colp = (r + ((c >> 3) << 2)) & 31;
        int key = ch * 32 + r;
        if (key < nk) {
            int kidx = idxp[key];
            const float4* kp = (const float4*)(kbase + (size_t)kidx * 64 + c);
            const float4* vp = (const float4*)(vbase + (size_t)kidx * 64 + c);
            float4 k0 = kp[0], k1 = kp[1];
            float4 v0 = vp[0], v1 = vp[1];
            Kb[(c + 0) * 40 + colp] = f2tf(k0.x); Kb[(c + 1) * 40 + colp] = f2tf(k0.y);
            Kb[(c + 2) * 40 + colp] = f2tf(k0.z); Kb[(c + 3) * 40 + colp] = f2tf(k0.w);
            Kb[(c + 4) * 40 + colp] = f2tf(k1.x); Kb[(c + 5) * 40 + colp] = f2tf(k1.y);
            Kb[(c + 6) * 40 + colp] = f2tf(k1.z); Kb[(c + 7) * 40 + colp] = f2tf(k1.w);
            Vb[(c + 0) * 40 + colp] = f2tf(v0.x); Vb[(c + 1) * 40 + colp] = f2tf(v0.y);
            Vb[(c + 2) * 40 + colp] = f2tf(v0.z); Vb[(c + 3) * 40 + colp] = f2tf(v0.w);
            Vb[(c + 4) * 40 + colp] = f2tf(v1.x); Vb[(c + 5) * 40 + colp] = f2tf(v1.y);
            Vb[(c + 6) * 40 + colp] = f2tf(v1.z); Vb[(c + 7) * 40 + colp] = f2tf(v1.w);
        } else {
            #pragma unroll
            for (int q = 0; q < 8; q++) {
                Kb[(c + q) * 40 + colp] = 0u;
                Vb[(c + q) * 40 + colp] = 0u;
            }
        }
    };

    float oacc[8][4];
    #pragma unroll
    for (int n = 0; n < 8; n++)
        #pragma unroll
        for (int j = 0; j < 4; j++) oacc[n][j] = 0.f;
    float mrow0 = -1e30f, mrow1 = -1e30f;
    float lrow0 = 0.f,    lrow1 = 0.f;

    unsigned* Pw = Psm + warp * 768;   // PsT[32][24]

    load_chunk(0);
    __syncthreads();

    for (int ch = 0; ch < nchunks; ch++) {
        const int cur = ch & 1;
        if (ch + 1 < nchunks) load_chunk(ch + 1);
        const unsigned* Kb = Ksm + cur * 2560;
        const unsigned* Vb = Vsm + cur * 2560;
        const int j0 = ch * 32;

        // S = (Q*scale) @ K^T
        float sc[4][4];
        #pragma unroll
        for (int n = 0; n < 4; n++)
            #pragma unroll
            for (int j = 0; j < 4; j++) sc[n][j] = 0.f;
        #pragma unroll
        for (int k = 0; k < 8; k++) {
            #pragma unroll
            for (int n = 0; n < 4; n++) {
                int col = (n * 8 + g + 4 * k) & 31;
                unsigned b0 = Kb[(k * 8 + t    ) * 40 + col];
                unsigned b1 = Kb[(k * 8 + t + 4) * 40 + col];
                mma_tf32(sc[n], qa[k][0], qa[k][1], qa[k][2], qa[k][3], b0, b1);
            }
        }

        float mx0 = -1e30f, mx1 = -1e30f;
        #pragma unroll
        for (int n = 0; n < 4; n++) {
            int c0 = j0 + n * 8 + 2 * t;
            bool ok0 = c0 < nk, ok1 = (c0 + 1) < nk;
            float v0 = ok0 ? sc[n][0] : -10000.0f;
            float v1 = ok1 ? sc[n][1] : -10000.0f;
            float v2 = ok0 ? sc[n][2] : -10000.0f;
            float v3 = ok1 ? sc[n][3] : -10000.0f;
            sc[n][0] = v0; sc[n][1] = v1; sc[n][2] = v2; sc[n][3] = v3;
            mx0 = fmaxf(mx0, fmaxf(v0, v1));
            mx1 = fmaxf(mx1, fmaxf(v2, v3));
        }
        mx0 = fmaxf(mx0, __shfl_xor_sync(0xffffffffu, mx0, 1));
        mx0 = fmaxf(mx0, __shfl_xor_sync(0xffffffffu, mx0, 2));
        mx1 = fmaxf(mx1, __shfl_xor_sync(0xffffffffu, mx1, 1));
        mx1 = fmaxf(mx1, __shfl_xor_sync(0xffffffffu, mx1, 2));

        float mn0 = fmaxf(mrow0, mx0), mn1 = fmaxf(mrow1, mx1);
        float f0 = __expf(mrow0 - mn0), f1 = __expf(mrow1 - mn1);
        float s0 = 0.f, s1 = 0.f;
        #pragma unroll
        for (int n = 0; n < 4; n++) {
            float p0 = __expf(sc[n][0] - mn0);
            float p1 = __expf(sc[n][1] - mn0);
            float p2 = __expf(sc[n][2] - mn1);
            float p3 = __expf(sc[n][3] - mn1);
            s0 += p0 + p1; s1 += p2 + p3;
            Pw[(n * 8 + 2 * t    ) * 24 + g    ] = f2tf(p0);
            Pw[(n * 8 + 2 * t + 1) * 24 + g    ] = f2tf(p1);
            Pw[(n * 8 + 2 * t    ) * 24 + g + 8] = f2tf(p2);
            Pw[(n * 8 + 2 * t + 1) * 24 + g + 8] = f2tf(p3);
        }
        s0 += __shfl_xor_sync(0xffffffffu, s0, 1);
        s0 += __shfl_xor_sync(0xffffffffu, s0, 2);
        s1 += __shfl_xor_sync(0xffffffffu, s1, 1);
        s1 += __shfl_xor_sync(0xffffffffu, s1, 2);

        lrow0 = lrow0 * f0 + s0;
        lrow1 = lrow1 * f1 + s1;
        mrow0 = mn0; mrow1 = mn1;
        #pragma unroll
        for (int n = 0; n < 8; n++) {
            oacc[n][0] *= f0; oacc[n][1] *= f0;
            oacc[n][2] *= f1; oacc[n][3] *= f1;
        }
        __syncwarp();

        // O += P @ V
        #pragma unroll
        for (int k = 0; k < 4; k++) {
            unsigned a0 = Pw[(k * 8 + t    ) * 24 + g    ];
            unsigned a1 = Pw[(k * 8 + t    ) * 24 + g + 8];
            unsigned a2 = Pw[(k * 8 + t + 4) * 24 + g    ];
            unsigned a3 = Pw[(k * 8 + t + 4) * 24 + g + 8];
            #pragma unroll
            for (int n = 0; n < 8; n++) {
                unsigned b0 = Vb[(n * 8 + g) * 40 + ((k * 8 + t     + 4 * n) & 31)];
                unsigned b1 = Vb[(n * 8 + g) * 40 + ((k * 8 + t + 4 + 4 * n) & 31)];
                mma_tf32(oacc[n], a0, a1, a2, a3, b0, b1);
            }
        }
        __syncthreads();
    }

    float r0 = 1.0f / lrow0, r1 = 1.0f / lrow1;
    int row0 = i0 + warp * 16 + g;
    int row1 = row0 + 8;
    float* o0 = g_O + ((size_t)(b * 1024 + row0)) * 512 + h * 64;
    float* o1 = g_O + ((size_t)(b * 1024 + row1)) * 512 + h * 64;
    #pragma unroll
    for (int n = 0; n < 8; n++) {
        int d = n * 8 + 2 * t;
        o0[d    ] = oacc[n][0] * r0 + qbase[(g    ) * 64 + d    ];
        o0[d + 1] = oacc[n][1] * r0 + qbase[(g    ) * 64 + d + 1];
        o1[d    ] = oacc[n][2] * r1 + qbase[(g + 8) * 64 + d    ];
        o1[d + 1] = oacc[n][3] * r1 + qbase[(g + 8) * 64 + d + 1];
    }
}

// ---------------- LayerNorm over rows of 512 -------------------------------
__global__ void ln_kernel(const float* __restrict__ gg, const float* __restrict__ bb,
                          float* __restrict__ extout, int sel)
{
    __shared__ float red[4];
    const float* in = (sel == 0) ? g_O : g_U;
    float* out = (sel == 0) ? g_X : extout;
    const int row = blockIdx.x, t = threadIdx.x;
    const float* p = in + (size_t)row * 512;
    float v[4];
    #pragma unroll
    for (int i = 0; i < 4; i++) v[i] = p[t + 128 * i];

    float s = v[0] + v[1] + v[2] + v[3];
    s = warpSum(s);
    if ((t & 31) == 0) red[t >> 5] = s;
    __syncthreads();
    s = red[0] + red[1] + red[2] + red[3];
    float mean = s * (1.f / 512.f);
    __syncthreads();

    float ss = 0.f;
    #pragma unroll
    for (int i = 0; i < 4; i++) { float d = v[i] - mean; ss += d * d; }
    ss = warpSum(ss);
    if ((t & 31) == 0) red[t >> 5] = ss;
    __syncthreads();
    ss = red[0] + red[1] + red[2] + red[3];
    float inv = rsqrtf(ss * (1.f / 512.f) + 1e-5f);

    #pragma unroll
    for (int i = 0; i < 4; i++) {
        int c = t + 128 * i;
        out[(size_t)row * 512 + c] = (v[i] - mean) * inv * gg[c] + bb[c];
    }
}

// ---------------- launch ----------------------------------------------------
extern "C" void kernel_launch(void* const* d_in, const int* in_sizes, int n_in,
                              void* d_out, int out_size)
{
    const float* Q    = (const float*)d_in[0];
    const float* K    = (const float*)d_in[1];
    const int*   mask = (const int*)  d_in[2];
    const float* Wq   = (const float*)d_in[3];
    const float* bq   = (const float*)d_in[4];
    const float* Wk   = (const float*)d_in[5];
    const float* bk   = (const float*)d_in[6];
    const float* Wv   = (const float*)d_in[7];
    const float* bv   = (const float*)d_in[8];
    const float* Wo   = (const float*)d_in[9];
    const float* bo   = (const float*)d_in[10];
    const float* g0   = (const float*)d_in[11];
    const float* b0   = (const float*)d_in[12];
    const float* g1   = (const float*)d_in[13];
    const float* b1   = (const float*)d_in[14];
    float* out = (float*)d_out;

    static bool attr_set = false;
    if (!attr_set) {
        cudaFuncSetAttribute(flash_attn, cudaFuncAttributeMaxDynamicSharedMemorySize,
                             SMEM_FLASH);
        attr_set = true;
    }

    compact_mask<<<BATCH, 1024>>>(mask);

    dim3 gqkv(DIM / 128, MROWS / 128, 3);   // (4, 64, 3) fused QKV projections
    gemm128<<<gqkv, 256>>>(Q, K, Wq, bq, Wk, bk, Wv, bv, 0);

    dim3 gf(NQ / 128, BH);                  // (8, 64)
    flash_attn<<<gf, 256, SMEM_FLASH>>>();

    ln_kernel<<<MROWS, 128>>>(g0, b0, nullptr, 0);

    dim3 go(DIM / 128, MROWS / 128, 1);     // (4, 64)
    gemm128<<<go, 256>>>(nullptr, nullptr, Wo, bo, nullptr, nullptr, nullptr, nullptr, 1);

    ln_kernel<<<MROWS, 128>>>(g1, b1, out, 1);
}

// round 7
// speedup vs baseline: 4.9917x; 1.1503x over previous
#include <cuda_runtime.h>
#include <math.h>

// Problem constants: B=8, NQ=NK=1024, D=512, H=8, dh=64
#define BATCH 8
#define NQ 1024
#define NK 1024
#define DIM 512
#define HEADS 8
#define DH 64
#define BH (BATCH*HEADS)          // 64
#define MROWS (BATCH*NQ)          // 8192

// ---------------- scratch (device globals; allocation-free) ----------------
__device__ float g_q[BH * NK * DH];   // full rows
__device__ float g_k[BH * NK * DH];   // COMPACTED rows (first cnt[b] valid)
__device__ float g_v[BH * NK * DH];   // COMPACTED rows
__device__ float g_O[MROWS * DIM];    // attention out
__device__ float g_U[MROWS * DIM];    // LN0(g_O) + relu(LN0(g_O)@Wo+bo)
__device__ float g_mu[MROWS];         // LN0 row mean
__device__ float g_rs[MROWS];         // LN0 row rstd
__device__ int   g_idx[BATCH * NK];
__device__ int   g_cnt[BATCH];

// ---------------- helpers ----------------
__device__ __forceinline__ float warpSum(float v) {
    #pragma unroll
    for (int o = 16; o > 0; o >>= 1) v += __shfl_xor_sync(0xffffffffu, v, o);
    return v;
}

__device__ __forceinline__ unsigned f2tf(float x) {
    unsigned u;
    asm("cvt.rna.tf32.f32 %0, %1;" : "=r"(u) : "f"(x));
    return u;
}

__device__ __forceinline__ void mma_tf32(float c[4],
                                         unsigned a0, unsigned a1, unsigned a2, unsigned a3,
                                         unsigned b0, unsigned b1)
{
    asm volatile(
        "mma.sync.aligned.m16n8k8.row.col.f32.tf32.tf32.f32 "
        "{%0,%1,%2,%3}, {%4,%5,%6,%7}, {%8,%9}, {%0,%1,%2,%3};\n"
        : "+f"(c[0]), "+f"(c[1]), "+f"(c[2]), "+f"(c[3])
        : "r"(a0), "r"(a1), "r"(a2), "r"(a3), "r"(b0), "r"(b1));
}

// ---------------- mask compaction ----------------
__global__ void compact_mask(const int* __restrict__ mask)
{
    __shared__ int warpsums[32];
    const int b = blockIdx.x, t = threadIdx.x;
    const int lane = t & 31, warp = t >> 5;
    int m = (mask[b * 1024 + t] != 0) ? 1 : 0;
    unsigned bal = __ballot_sync(0xffffffffu, m);
    int pre = __popc(bal & ((1u << lane) - 1u));
    if (lane == 0) warpsums[warp] = __popc(bal);
    __syncthreads();
    if (warp == 0) {
        int v = warpsums[lane];
        #pragma unroll
        for (int o = 1; o < 32; o <<= 1) {
            int u = __shfl_up_sync(0xffffffffu, v, o);
            if (lane >= o) v += u;
        }
        warpsums[lane] = v;
    }
    __syncthreads();
    int base = (warp == 0) ? 0 : warpsums[warp - 1];
    if (m) g_idx[b * 1024 + base + pre] = t;
    if (t == 1023) g_cnt[b] = warpsums[31];
}

// ---------------- 128x128 tensor-core GEMM ---------------------------------
// MODE 0 (grid.z=3): z=0: Q@Wq+bq -> g_q (full rows)
//                    z=1: K@Wk+bk -> g_k (COMPACTED rows, gathered A)
//                    z=2: K@Wv+bv -> g_v (COMPACTED rows)
//                    head layout out[(b*H+h)*1024 + n_local][d]
// MODE 1 (grid.z=1): A = LN0(g_O) on the fly; g_U = LN0(g_O) + relu(A@W+bias)
//                    params: W=p2, bias=p3, gamma=p4, beta=p5
template<int MODE>
__global__ void __launch_bounds__(256, 2) gemm128(
    const float* __restrict__ p0, const float* __restrict__ p1,
    const float* __restrict__ p2, const float* __restrict__ p3,
    const float* __restrict__ p4, const float* __restrict__ p5,
    const float* __restrict__ p6, const float* __restrict__ p7)
{
    __shared__ unsigned AsT[2][16][136];
    __shared__ unsigned Bs[2][16][136];
    const int z = blockIdx.z;
    const int n0 = blockIdx.x * 128;
    const int bb = blockIdx.y >> 3;          // batch
    const int tyl = blockIdx.y & 7;          // tile within batch
    const int m0 = blockIdx.y * 128;         // global row base (MODE 1)

    const float* A; const float* W; const float* bias; float* outp;
    const float* gamma = p4; const float* beta = p5;
    if (MODE == 0) {
        A    = (z == 0) ? p0 : p1;
        W    = (z == 0) ? p2 : (z == 1) ? p4 : p6;
        bias = (z == 0) ? p3 : (z == 1) ? p5 : p7;
        outp = (z == 0) ? g_q : (z == 1) ? g_k : g_v;
    } else {
        A = (const float*)g_O; W = p2; bias = p3; outp = g_U;
    }

    int cnt = 1024;
    if (MODE == 0 && z > 0) {
        cnt = g_cnt[bb];
        if (tyl * 128 >= cnt) return;        // whole tile beyond compacted rows
    }

    const int tid = threadIdx.x;
    const int warp = tid >> 5, lane = tid & 31;
    const int wm = warp >> 2, wn = warp & 3;
    const int g = lane >> 2, t = lane & 3;
    const int mbase = wm * 64;
    const int nbase = wn * 32;

    // per-thread fixed A rows (local tile rows r1, r1+64)
    const int r1 = tid >> 2;
    const int c4 = (tid & 3) << 2;
    const int sw = (tid & 3) << 3;           // store swizzle
    const float* arow1; const float* arow2;
    float mu1 = 0.f, rs1 = 0.f, mu2 = 0.f, rs2 = 0.f;
    {
        int li1 = tyl * 128 + r1;
        int li2 = li1 + 64;
        if (MODE == 0 && z > 0) {
            int gi1 = (li1 < cnt) ? g_idx[bb * 1024 + li1] : 0;
            int gi2 = (li2 < cnt) ? g_idx[bb * 1024 + li2] : 0;
            arow1 = A + ((size_t)bb * 1024 + gi1) * 512;
            arow2 = A + ((size_t)bb * 1024 + gi2) * 512;
        } else {
            arow1 = A + ((size_t)bb * 1024 + li1) * 512;
            arow2 = A + ((size_t)bb * 1024 + li2) * 512;
        }
        if (MODE == 1) {
            mu1 = g_mu[m0 + r1];      rs1 = g_rs[m0 + r1];
            mu2 = g_mu[m0 + r1 + 64]; rs2 = g_rs[m0 + r1 + 64];
        }
    }

    auto loadAB = [&](int k0, int bufi) {
        float4 a1 = *(const float4*)(arow1 + k0 + c4);
        float4 a2 = *(const float4*)(arow2 + k0 + c4);
        if (MODE == 1) {
            float4 gm = *(const float4*)(gamma + k0 + c4);
            float4 bt = *(const float4*)(beta  + k0 + c4);
            a1.x = (a1.x - mu1) * rs1 * gm.x + bt.x;
            a1.y = (a1.y - mu1) * rs1 * gm.y + bt.y;
            a1.z = (a1.z - mu1) * rs1 * gm.z + bt.z;
            a1.w = (a1.w - mu1) * rs1 * gm.w + bt.w;
            a2.x = (a2.x - mu2) * rs2 * gm.x + bt.x;
            a2.y = (a2.y - mu2) * rs2 * gm.y + bt.y;
            a2.z = (a2.z - mu2) * rs2 * gm.z + bt.z;
            a2.w = (a2.w - mu2) * rs2 * gm.w + bt.w;
        }
        int rc1 = r1 ^ sw, rc2 = (r1 + 64) ^ sw;
        AsT[bufi][c4 + 0][rc1] = f2tf(a1.x); AsT[bufi][c4 + 1][rc1] = f2tf(a1.y);
        AsT[bufi][c4 + 2][rc1] = f2tf(a1.z); AsT[bufi][c4 + 3][rc1] = f2tf(a1.w);
        AsT[bufi][c4 + 0][rc2] = f2tf(a2.x); AsT[bufi][c4 + 1][rc2] = f2tf(a2.y);
        AsT[bufi][c4 + 2][rc2] = f2tf(a2.z); AsT[bufi][c4 + 3][rc2] = f2tf(a2.w);
        #pragma unroll
        for (int it = 0; it < 2; it++) {
            int idx = tid + it * 256;
            int r = idx >> 5, cc = (idx & 31) << 2;
            float4 w = *(const float4*)(W + (size_t)(k0 + r) * 512 + n0 + cc);
            uint4 pw = make_uint4(f2tf(w.x), f2tf(w.y), f2tf(w.z), f2tf(w.w));
            *(uint4*)&Bs[bufi][r][cc] = pw;
        }
    };

    float acc[4][4][4];
    #pragma unroll
    for (int i = 0; i < 4; i++)
        #pragma unroll
        for (int j = 0; j < 4; j++)
            #pragma unroll
            for (int q = 0; q < 4; q++) acc[i][j][q] = 0.f;

    loadAB(0, 0);
    __syncthreads();

    for (int it = 0; it < 32; it++) {
        int cur = it & 1;
        if (it < 31) loadAB((it + 1) * 16, cur ^ 1);
        #pragma unroll
        for (int ks = 0; ks < 2; ks++) {
            int kk = ks * 8;
            int sw0 = (kk >> 2) << 3;
            int sw1 = ((kk + 4) >> 2) << 3;
            unsigned av[4][4], bv[4][2];
            #pragma unroll
            for (int i = 0; i < 4; i++) {
                int mb = mbase + i * 16;
                av[i][0] = AsT[cur][kk + t    ][(mb + g    ) ^ sw0];
                av[i][1] = AsT[cur][kk + t    ][(mb + g + 8) ^ sw0];
                av[i][2] = AsT[cur][kk + t + 4][(mb + g    ) ^ sw1];
                av[i][3] = AsT[cur][kk + t + 4][(mb + g + 8) ^ sw1];
            }
            #pragma unroll
            for (int j = 0; j < 4; j++) {
                bv[j][0] = Bs[cur][kk + t    ][nbase + j * 8 + g];
                bv[j][1] = Bs[cur][kk + t + 4][nbase + j * 8 + g];
            }
            #pragma unroll
            for (int i = 0; i < 4; i++)
                #pragma unroll
                for (int j = 0; j < 4; j++)
                    mma_tf32(acc[i][j], av[i][0], av[i][1], av[i][2], av[i][3],
                             bv[j][0], bv[j][1]);
        }
        __syncthreads();
    }

    #pragma unroll
    for (int i = 0; i < 4; i++) {
        int lr0 = mbase + i * 16 + g;        // local tile row
        #pragma unroll
        for (int j = 0; j < 4; j++) {
            int c0 = n0 + nbase + j * 8 + 2 * t;
            #pragma unroll
            for (int q = 0; q < 4; q++) {
                int lr = lr0 + (q >> 1) * 8;
                int c  = c0 + (q & 1);
                float val = acc[i][j][q] + bias[c];
                if (MODE == 0) {
                    int n = tyl * 128 + lr;  // row within batch (compacted for z>0)
                    int h = c >> 6, d = c & 63;
                    outp[(((size_t)(bb * HEADS + h)) * 1024 + n) * 64 + d] = val;
                } else {
                    int r = m0 + lr;
                    float xv = (g_O[(size_t)r * 512 + c] - g_mu[r]) * g_rs[r]
                               * gamma[c] + beta[c];
                    outp[(size_t)r * 512 + c] = xv + fmaxf(val, 0.f);
                }
            }
        }
    }
}

// ---------------- fused flash attention (contiguous compacted K/V) ---------
#define KS_OFF 0
#define VS_OFF (2*64*40)
#define PS_OFF (4*64*40)
#define SMEM_FLASH ((4*64*40 + 8*32*24) * 4)

__global__ void __launch_bounds__(256) flash_attn()
{
    extern __shared__ unsigned sm[];
    unsigned* Ksm = sm + KS_OFF;
    unsigned* Vsm = sm + VS_OFF;
    unsigned* Psm = sm + PS_OFF;

    const int bh = blockIdx.y;
    const int b = bh >> 3, h = bh & 7;
    const int i0 = blockIdx.x * 128;
    const int tid = threadIdx.x;
    const int warp = tid >> 5, lane = tid & 31;
    const int g = lane >> 2, t = lane & 3;

    const int nk = g_cnt[b];
    const int nchunks = (nk + 31) >> 5;
    const float* kbase = g_k + (size_t)bh * 1024 * 64;
    const float* vbase = g_v + (size_t)bh * 1024 * 64;
    const float scale = 0.044194173824159216f; // 1/sqrt(512)

    const float* qbase = g_q + ((size_t)bh * 1024 + i0 + warp * 16) * 64;
    unsigned qa[8][4];
    #pragma unroll
    for (int k = 0; k < 8; k++) {
        qa[k][0] = f2tf(qbase[(g    ) * 64 + k * 8 + t    ] * scale);
        qa[k][1] = f2tf(qbase[(g + 8) * 64 + k * 8 + t    ] * scale);
        qa[k][2] = f2tf(qbase[(g    ) * 64 + k * 8 + t + 4] * scale);
        qa[k][3] = f2tf(qbase[(g + 8) * 64 + k * 8 + t + 4] * scale);
    }

    auto load_chunk = [&](int ch) {
        int bufi = ch & 1;
        unsigned* Kb = Ksm + bufi * 2560;
        unsigned* Vb = Vsm + bufi * 2560;
        int r = tid >> 3;
        int c = (tid & 7) * 8;
        int colp = (r + ((c >> 3) << 2)) & 31;
        int key = ch * 32 + r;
        if (key < nk) {
            const float4* kp = (const float4*)(kbase + (size_t)key * 64 + c);
            const float4* vp = (const float4*)(vbase + (size_t)key * 64 + c);
            float4 k0 = kp[0], k1 = kp[1];
            float4 v0 = vp[0], v1 = vp[1];
            Kb[(c + 0) * 40 + colp] = f2tf(k0.x); Kb[(c + 1) * 40 + colp] = f2tf(k0.y);
            Kb[(c + 2) * 40 + colp] = f2tf(k0.z); Kb[(c + 3) * 40 + colp] = f2tf(k0.w);
            Kb[(c + 4) * 40 + colp] = f2tf(k1.x); Kb[(c + 5) * 40 + colp] = f2tf(k1.y);
            Kb[(c + 6) * 40 + colp] = f2tf(k1.z); Kb[(c + 7) * 40 + colp] = f2tf(k1.w);
            Vb[(c + 0) * 40 + colp] = f2tf(v0.x); Vb[(c + 1) * 40 + colp] = f2tf(v0.y);
            Vb[(c + 2) * 40 + colp] = f2tf(v0.z); Vb[(c + 3) * 40 + colp] = f2tf(v0.w);
            Vb[(c + 4) * 40 + colp] = f2tf(v1.x); Vb[(c + 5) * 40 + colp] = f2tf(v1.y);
            Vb[(c + 6) * 40 + colp] = f2tf(v1.z); Vb[(c + 7) * 40 + colp] = f2tf(v1.w);
        } else {
            #pragma unroll
            for (int q = 0; q < 8; q++) {
                Kb[(c + q) * 40 + colp] = 0u;
                Vb[(c + q) * 40 + colp] = 0u;
            }
        }
    };

    float oacc[8][4];
    #pragma unroll
    for (int n = 0; n < 8; n++)
        #pragma unroll
        for (int j = 0; j < 4; j++) oacc[n][j] = 0.f;
    float mrow0 = -1e30f, mrow1 = -1e30f;
    float lrow0 = 0.f,    lrow1 = 0.f;

    unsigned* Pw = Psm + warp * 768;

    load_chunk(0);
    __syncthreads();

    for (int ch = 0; ch < nchunks; ch++) {
        const int cur = ch & 1;
        if (ch + 1 < nchunks) load_chunk(ch + 1);
        const unsigned* Kb = Ksm + cur * 2560;
        const unsigned* Vb = Vsm + cur * 2560;
        const int j0 = ch * 32;

        float sc[4][4];
        #pragma unroll
        for (int n = 0; n < 4; n++)
            #pragma unroll
            for (int j = 0; j < 4; j++) sc[n][j] = 0.f;
        #pragma unroll
        for (int k = 0; k < 8; k++) {
            #pragma unroll
            for (int n = 0; n < 4; n++) {
                int col = (n * 8 + g + 4 * k) & 31;
                unsigned b0 = Kb[(k * 8 + t    ) * 40 + col];
                unsigned b1 = Kb[(k * 8 + t + 4) * 40 + col];
                mma_tf32(sc[n], qa[k][0], qa[k][1], qa[k][2], qa[k][3], b0, b1);
            }
        }

        float mx0 = -1e30f, mx1 = -1e30f;
        #pragma unroll
        for (int n = 0; n < 4; n++) {
            int c0 = j0 + n * 8 + 2 * t;
            bool ok0 = c0 < nk, ok1 = (c0 + 1) < nk;
            float v0 = ok0 ? sc[n][0] : -10000.0f;
            float v1 = ok1 ? sc[n][1] : -10000.0f;
            float v2 = ok0 ? sc[n][2] : -10000.0f;
            float v3 = ok1 ? sc[n][3] : -10000.0f;
            sc[n][0] = v0; sc[n][1] = v1; sc[n][2] = v2; sc[n][3] = v3;
            mx0 = fmaxf(mx0, fmaxf(v0, v1));
            mx1 = fmaxf(mx1, fmaxf(v2, v3));
        }
        mx0 = fmaxf(mx0, __shfl_xor_sync(0xffffffffu, mx0, 1));
        mx0 = fmaxf(mx0, __shfl_xor_sync(0xffffffffu, mx0, 2));
        mx1 = fmaxf(mx1, __shfl_xor_sync(0xffffffffu, mx1, 1));
        mx1 = fmaxf(mx1, __shfl_xor_sync(0xffffffffu, mx1, 2));

        float mn0 = fmaxf(mrow0, mx0), mn1 = fmaxf(mrow1, mx1);
        float f0 = __expf(mrow0 - mn0), f1 = __expf(mrow1 - mn1);
        float s0 = 0.f, s1 = 0.f;
        #pragma unroll
        for (int n = 0; n < 4; n++) {
            float p0 = __expf(sc[n][0] - mn0);
            float p1 = __expf(sc[n][1] - mn0);
            float p2 = __expf(sc[n][2] - mn1);
            float p3 = __expf(sc[n][3] - mn1);
            s0 += p0 + p1; s1 += p2 + p3;
            Pw[(n * 8 + 2 * t    ) * 24 + g    ] = f2tf(p0);
            Pw[(n * 8 + 2 * t + 1) * 24 + g    ] = f2tf(p1);
            Pw[(n * 8 + 2 * t    ) * 24 + g + 8] = f2tf(p2);
            Pw[(n * 8 + 2 * t + 1) * 24 + g + 8] = f2tf(p3);
        }
        s0 += __shfl_xor_sync(0xffffffffu, s0, 1);
        s0 += __shfl_xor_sync(0xffffffffu, s0, 2);
        s1 += __shfl_xor_sync(0xffffffffu, s1, 1);
        s1 += __shfl_xor_sync(0xffffffffu, s1, 2);

        lrow0 = lrow0 * f0 + s0;
        lrow1 = lrow1 * f1 + s1;
        mrow0 = mn0; mrow1 = mn1;
        #pragma unroll
        for (int n = 0; n < 8; n++) {
            oacc[n][0] *= f0; oacc[n][1] *= f0;
            oacc[n][2] *= f1; oacc[n][3] *= f1;
        }
        __syncwarp();

        #pragma unroll
        for (int k = 0; k < 4; k++) {
            unsigned a0 = Pw[(k * 8 + t    ) * 24 + g    ];
            unsigned a1 = Pw[(k * 8 + t    ) * 24 + g + 8];
            unsigned a2 = Pw[(k * 8 + t + 4) * 24 + g    ];
            unsigned a3 = Pw[(k * 8 + t + 4) * 24 + g + 8];
            #pragma unroll
            for (int n = 0; n < 8; n++) {
                unsigned b0 = Vb[(n * 8 + g) * 40 + ((k * 8 + t     + 4 * n) & 31)];
                unsigned b1 = Vb[(n * 8 + g) * 40 + ((k * 8 + t + 4 + 4 * n) & 31)];
                mma_tf32(oacc[n], a0, a1, a2, a3, b0, b1);
            }
        }
        __syncthreads();
    }

    float r0 = 1.0f / lrow0, r1 = 1.0f / lrow1;
    int row0 = i0 + warp * 16 + g;
    int row1 = row0 + 8;
    float* o0 = g_O + ((size_t)(b * 1024 + row0)) * 512 + h * 64;
    float* o1 = g_O + ((size_t)(b * 1024 + row1)) * 512 + h * 64;
    #pragma unroll
    for (int n = 0; n < 8; n++) {
        int d = n * 8 + 2 * t;
        o0[d    ] = oacc[n][0] * r0 + qbase[(g    ) * 64 + d    ];
        o0[d + 1] = oacc[n][1] * r0 + qbase[(g    ) * 64 + d + 1];
        o1[d    ] = oacc[n][2] * r1 + qbase[(g + 8) * 64 + d    ];
        o1[d + 1] = oacc[n][3] * r1 + qbase[(g + 8) * 64 + d + 1];
    }
}

// ---------------- LN0 row stats over g_O ------------------------------------
__global__ void ln_stats()
{
    __shared__ float red[4];
    const int row = blockIdx.x, t = threadIdx.x;
    const float* p = g_O + (size_t)row * 512;
    float v[4];
    #pragma unroll
    for (int i = 0; i < 4; i++) v[i] = p[t + 128 * i];

    float s = v[0] + v[1] + v[2] + v[3];
    s = warpSum(s);
    if ((t & 31) == 0) red[t >> 5] = s;
    __syncthreads();
    s = red[0] + red[1] + red[2] + red[3];
    float mean = s * (1.f / 512.f);
    __syncthreads();

    float ss = 0.f;
    #pragma unroll
    for (int i = 0; i < 4; i++) { float d = v[i] - mean; ss += d * d; }
    ss = warpSum(ss);
    if ((t & 31) == 0) red[t >> 5] = ss;
    __syncthreads();
    ss = red[0] + red[1] + red[2] + red[3];
    if (t == 0) {
        g_mu[row] = mean;
        g_rs[row] = rsqrtf(ss * (1.f / 512.f) + 1e-5f);
    }
}

// ---------------- final LayerNorm: g_U -> out --------------------------------
__global__ void ln_final(const float* __restrict__ gg, const float* __restrict__ bb,
                         float* __restrict__ out)
{
    __shared__ float red[4];
    const int row = blockIdx.x, t = threadIdx.x;
    const float* p = g_U + (size_t)row * 512;
    float v[4];
    #pragma unroll
    for (int i = 0; i < 4; i++) v[i] = p[t + 128 * i];

    float s = v[0] + v[1] + v[2] + v[3];
    s = warpSum(s);
    if ((t & 31) == 0) red[t >> 5] = s;
    __syncthreads();
    s = red[0] + red[1] + red[2] + red[3];
    float mean = s * (1.f / 512.f);
    __syncthreads();

    float ss = 0.f;
    #pragma unroll
    for (int i = 0; i < 4; i++) { float d = v[i] - mean; ss += d * d; }
    ss = warpSum(ss);
    if ((t & 31) == 0) red[t >> 5] = ss;
    __syncthreads();
    ss = red[0] + red[1] + red[2] + red[3];
    float inv = rsqrtf(ss * (1.f / 512.f) + 1e-5f);

    #pragma unroll
    for (int i = 0; i < 4; i++) {
        int c = t + 128 * i;
        out[(size_t)row * 512 + c] = (v[i] - mean) * inv * gg[c] + bb[c];
    }
}

// ---------------- launch ----------------------------------------------------
extern "C" void kernel_launch(void* const* d_in, const int* in_sizes, int n_in,
                              void* d_out, int out_size)
{
    const float* Q    = (const float*)d_in[0];
    const float* K    = (const float*)d_in[1];
    const int*   mask = (const int*)  d_in[2];
    const float* Wq   = (const float*)d_in[3];
    const float* bq   = (const float*)d_in[4];
    const float* Wk   = (const float*)d_in[5];
    const float* bk   = (const float*)d_in[6];
    const float* Wv   = (const float*)d_in[7];
    const float* bv   = (const float*)d_in[8];
    const float* Wo   = (const float*)d_in[9];
    const float* bo   = (const float*)d_in[10];
    const float* g0   = (const float*)d_in[11];
    const float* b0   = (const float*)d_in[12];
    const float* g1   = (const float*)d_in[13];
    const float* b1   = (const float*)d_in[14];
    float* out = (float*)d_out;

    static bool attr_set = false;
    if (!attr_set) {
        cudaFuncSetAttribute(flash_attn, cudaFuncAttributeMaxDynamicSharedMemorySize,
                             SMEM_FLASH);
        attr_set = true;
    }

    compact_mask<<<BATCH, 1024>>>(mask);

    dim3 gqkv(DIM / 128, MROWS / 128, 3);   // (4, 64, 3)
    gemm128<0><<<gqkv, 256>>>(Q, K, Wq, bq, Wk, bk, Wv, bv);

    dim3 gf(NQ / 128, BH);                  // (8, 64)
    flash_attn<<<gf, 256, SMEM_FLASH>>>();

    ln_stats<<<MROWS, 128>>>();

    dim3 go(DIM / 128, MROWS / 128, 1);     // (4, 64)
    gemm128<1><<<go, 256>>>(nullptr, nullptr, Wo, bo, g0, b0, nullptr, nullptr);

    ln_final<<<MROWS, 128>>>(g1, b1, out);
}

// round 8
// speedup vs baseline: 5.4597x; 1.0938x over previous
#include <cuda_runtime.h>
#include <math.h>

// Problem constants: B=8, NQ=NK=1024, D=512, H=8, dh=64
#define BATCH 8
#define NQ 1024
#define NK 1024
#define DIM 512
#define HEADS 8
#define DH 64
#define BH (BATCH*HEADS)          // 64
#define MROWS (BATCH*NQ)          // 8192

// ---------------- scratch (device globals; allocation-free) ----------------
__device__ float g_q[BH * NK * DH];   // full rows, f32
__device__ float g_k[BH * NK * DH];   // COMPACTED rows, tf32-rounded bits
__device__ float g_v[BH * NK * DH];   // COMPACTED rows, tf32-rounded bits
__device__ float g_O[MROWS * DIM];
__device__ float g_U[MROWS * DIM];
__device__ float g_mu[MROWS];
__device__ float g_rs[MROWS];
__device__ int   g_idx[BATCH * NK];
__device__ int   g_cnt[BATCH];

// ---------------- helpers ----------------
__device__ __forceinline__ float warpSum(float v) {
    #pragma unroll
    for (int o = 16; o > 0; o >>= 1) v += __shfl_xor_sync(0xffffffffu, v, o);
    return v;
}

__device__ __forceinline__ unsigned f2tf(float x) {
    unsigned u;
    asm("cvt.rna.tf32.f32 %0, %1;" : "=r"(u) : "f"(x));
    return u;
}

__device__ __forceinline__ void mma_tf32(float c[4],
                                         unsigned a0, unsigned a1, unsigned a2, unsigned a3,
                                         unsigned b0, unsigned b1)
{
    asm volatile(
        "mma.sync.aligned.m16n8k8.row.col.f32.tf32.tf32.f32 "
        "{%0,%1,%2,%3}, {%4,%5,%6,%7}, {%8,%9}, {%0,%1,%2,%3};\n"
        : "+f"(c[0]), "+f"(c[1]), "+f"(c[2]), "+f"(c[3])
        : "r"(a0), "r"(a1), "r"(a2), "r"(a3), "r"(b0), "r"(b1));
}

__device__ __forceinline__ void cp16(unsigned smem_addr, const void* gptr, int src_sz) {
    asm volatile("cp.async.cg.shared.global [%0], [%1], 16, %2;\n"
                 :: "r"(smem_addr), "l"(gptr), "r"(src_sz));
}

// ---------------- mask compaction ----------------
__global__ void compact_mask(const int* __restrict__ mask)
{
    __shared__ int warpsums[32];
    const int b = blockIdx.x, t = threadIdx.x;
    const int lane = t & 31, warp = t >> 5;
    int m = (mask[b * 1024 + t] != 0) ? 1 : 0;
    unsigned bal = __ballot_sync(0xffffffffu, m);
    int pre = __popc(bal & ((1u << lane) - 1u));
    if (lane == 0) warpsums[warp] = __popc(bal);
    __syncthreads();
    if (warp == 0) {
        int v = warpsums[lane];
        #pragma unroll
        for (int o = 1; o < 32; o <<= 1) {
            int u = __shfl_up_sync(0xffffffffu, v, o);
            if (lane >= o) v += u;
        }
        warpsums[lane] = v;
    }
    __syncthreads();
    int base = (warp == 0) ? 0 : warpsums[warp - 1];
    if (m) g_idx[b * 1024 + base + pre] = t;
    if (t == 1023) g_cnt[b] = warpsums[31];
}

// ---------------- 128x128 tensor-core GEMM ---------------------------------
// MODE 0 (grid.z=3): z=0: Q@Wq+bq -> g_q ; z=1/2: K@{Wk,Wv}+b -> g_k/g_v
//                    (compacted rows for z>0, values tf32-rounded)
// MODE 1 (grid.z=1): A = LN0(g_O) on the fly; g_U = LN0(g_O) + relu(A@W+bias)
template<int MODE>
__global__ void __launch_bounds__(256, 2) gemm128(
    const float* __restrict__ p0, const float* __restrict__ p1,
    const float* __restrict__ p2, const float* __restrict__ p3,
    const float* __restrict__ p4, const float* __restrict__ p5,
    const float* __restrict__ p6, const float* __restrict__ p7)
{
    __shared__ unsigned AsT[2][16][136];
    __shared__ unsigned Bs[2][16][136];
    const int z = blockIdx.z;
    const int n0 = blockIdx.x * 128;
    const int bb = blockIdx.y >> 3;
    const int tyl = blockIdx.y & 7;
    const int m0 = blockIdx.y * 128;

    const float* A; const float* W; const float* bias; float* outp;
    const float* gamma = p4; const float* beta = p5;
    if (MODE == 0) {
        A    = (z == 0) ? p0 : p1;
        W    = (z == 0) ? p2 : (z == 1) ? p4 : p6;
        bias = (z == 0) ? p3 : (z == 1) ? p5 : p7;
        outp = (z == 0) ? g_q : (z == 1) ? g_k : g_v;
    } else {
        A = (const float*)g_O; W = p2; bias = p3; outp = g_U;
    }

    int cnt = 1024;
    if (MODE == 0 && z > 0) {
        cnt = g_cnt[bb];
        if (tyl * 128 >= cnt) return;
    }

    const int tid = threadIdx.x;
    const int warp = tid >> 5, lane = tid & 31;
    const int wm = warp >> 2, wn = warp & 3;
    const int g = lane >> 2, t = lane & 3;
    const int mbase = wm * 64;
    const int nbase = wn * 32;

    const int r1 = tid >> 2;
    const int c4 = (tid & 3) << 2;
    const int sw = (tid & 3) << 3;
    const float* arow1; const float* arow2;
    float mu1 = 0.f, rs1 = 0.f, mu2 = 0.f, rs2 = 0.f;
    {
        int li1 = tyl * 128 + r1;
        int li2 = li1 + 64;
        if (MODE == 0 && z > 0) {
            int gi1 = (li1 < cnt) ? g_idx[bb * 1024 + li1] : 0;
            int gi2 = (li2 < cnt) ? g_idx[bb * 1024 + li2] : 0;
            arow1 = A + ((size_t)bb * 1024 + gi1) * 512;
            arow2 = A + ((size_t)bb * 1024 + gi2) * 512;
        } else {
            arow1 = A + ((size_t)bb * 1024 + li1) * 512;
            arow2 = A + ((size_t)bb * 1024 + li2) * 512;
        }
        if (MODE == 1) {
            mu1 = g_mu[m0 + r1];      rs1 = g_rs[m0 + r1];
            mu2 = g_mu[m0 + r1 + 64]; rs2 = g_rs[m0 + r1 + 64];
        }
    }

    auto loadAB = [&](int k0, int bufi) {
        float4 a1 = *(const float4*)(arow1 + k0 + c4);
        float4 a2 = *(const float4*)(arow2 + k0 + c4);
        if (MODE == 1) {
            float4 gm = *(const float4*)(gamma + k0 + c4);
            float4 bt = *(const float4*)(beta  + k0 + c4);
            a1.x = (a1.x - mu1) * rs1 * gm.x + bt.x;
            a1.y = (a1.y - mu1) * rs1 * gm.y + bt.y;
            a1.z = (a1.z - mu1) * rs1 * gm.z + bt.z;
            a1.w = (a1.w - mu1) * rs1 * gm.w + bt.w;
            a2.x = (a2.x - mu2) * rs2 * gm.x + bt.x;
            a2.y = (a2.y - mu2) * rs2 * gm.y + bt.y;
            a2.z = (a2.z - mu2) * rs2 * gm.z + bt.z;
            a2.w = (a2.w - mu2) * rs2 * gm.w + bt.w;
        }
        int rc1 = r1 ^ sw, rc2 = (r1 + 64) ^ sw;
        AsT[bufi][c4 + 0][rc1] = f2tf(a1.x); AsT[bufi][c4 + 1][rc1] = f2tf(a1.y);
        AsT[bufi][c4 + 2][rc1] = f2tf(a1.z); AsT[bufi][c4 + 3][rc1] = f2tf(a1.w);
        AsT[bufi][c4 + 0][rc2] = f2tf(a2.x); AsT[bufi][c4 + 1][rc2] = f2tf(a2.y);
        AsT[bufi][c4 + 2][rc2] = f2tf(a2.z); AsT[bufi][c4 + 3][rc2] = f2tf(a2.w);
        #pragma unroll
        for (int it = 0; it < 2; it++) {
            int idx = tid + it * 256;
            int r = idx >> 5, cc = (idx & 31) << 2;
            float4 w = *(const float4*)(W + (size_t)(k0 + r) * 512 + n0 + cc);
            uint4 pw = make_uint4(f2tf(w.x), f2tf(w.y), f2tf(w.z), f2tf(w.w));
            *(uint4*)&Bs[bufi][r][cc] = pw;
        }
    };

    float acc[4][4][4];
    #pragma unroll
    for (int i = 0; i < 4; i++)
        #pragma unroll
        for (int j = 0; j < 4; j++)
            #pragma unroll
            for (int q = 0; q < 4; q++) acc[i][j][q] = 0.f;

    loadAB(0, 0);
    __syncthreads();

    for (int it = 0; it < 32; it++) {
        int cur = it & 1;
        if (it < 31) loadAB((it + 1) * 16, cur ^ 1);
        #pragma unroll
        for (int ks = 0; ks < 2; ks++) {
            int kk = ks * 8;
            int sw0 = (kk >> 2) << 3;
            int sw1 = ((kk + 4) >> 2) << 3;
            unsigned av[4][4], bv[4][2];
            #pragma unroll
            for (int i = 0; i < 4; i++) {
                int mb = mbase + i * 16;
                av[i][0] = AsT[cur][kk + t    ][(mb + g    ) ^ sw0];
                av[i][1] = AsT[cur][kk + t    ][(mb + g + 8) ^ sw0];
                av[i][2] = AsT[cur][kk + t + 4][(mb + g    ) ^ sw1];
                av[i][3] = AsT[cur][kk + t + 4][(mb + g + 8) ^ sw1];
            }
            #pragma unroll
            for (int j = 0; j < 4; j++) {
                bv[j][0] = Bs[cur][kk + t    ][nbase + j * 8 + g];
                bv[j][1] = Bs[cur][kk + t + 4][nbase + j * 8 + g];
            }
            #pragma unroll
            for (int i = 0; i < 4; i++)
                #pragma unroll
                for (int j = 0; j < 4; j++)
                    mma_tf32(acc[i][j], av[i][0], av[i][1], av[i][2], av[i][3],
                             bv[j][0], bv[j][1]);
        }
        __syncthreads();
    }

    #pragma unroll
    for (int i = 0; i < 4; i++) {
        int lr0 = mbase + i * 16 + g;
        #pragma unroll
        for (int j = 0; j < 4; j++) {
            int c0 = n0 + nbase + j * 8 + 2 * t;
            #pragma unroll
            for (int q = 0; q < 4; q++) {
                int lr = lr0 + (q >> 1) * 8;
                int c  = c0 + (q & 1);
                float val = acc[i][j][q] + bias[c];
                if (MODE == 0) {
                    int n = tyl * 128 + lr;
                    int h = c >> 6, d = c & 63;
                    // K/V: round to tf32 now so flash can consume raw bits
                    float sval = (z == 0) ? val : __uint_as_float(f2tf(val));
                    outp[(((size_t)(bb * HEADS + h)) * 1024 + n) * 64 + d] = sval;
                } else {
                    int r = m0 + lr;
                    float xv = (g_O[(size_t)r * 512 + c] - g_mu[r]) * g_rs[r]
                               * gamma[c] + beta[c];
                    outp[(size_t)r * 512 + c] = xv + fmaxf(val, 0.f);
                }
            }
        }
    }
}

// ---------------- fused flash attention (cp.async, natural layouts) --------
// dyn smem words: Ks[2][32][68], Vs[2][32][72], Ps[8][32][24]
#define KSTRIDE 68
#define VSTRIDE 72
#define KS_OFF 0
#define VS_OFF (2*32*KSTRIDE)                       // 4352
#define PS_OFF (VS_OFF + 2*32*VSTRIDE)              // 8960
#define SMEM_FLASH ((PS_OFF + 8*32*24) * 4)

__global__ void __launch_bounds__(256) flash_attn()
{
    extern __shared__ unsigned sm[];
    unsigned smem_u32;
    {
        unsigned long long p;
        asm("cvta.to.shared.u64 %0, %1;" : "=l"(p) : "l"(sm));
        smem_u32 = (unsigned)p;
    }

    const int bh = blockIdx.y;
    const int b = bh >> 3, h = bh & 7;
    const int i0 = blockIdx.x * 128;
    const int tid = threadIdx.x;
    const int warp = tid >> 5, lane = tid & 31;
    const int g = lane >> 2, t = lane & 3;

    const int nk = g_cnt[b];
    const int nchunks = (nk + 31) >> 5;
    const float* kbase = g_k + (size_t)bh * 1024 * 64;
    const float* vbase = g_v + (size_t)bh * 1024 * 64;
    const float scale = 0.044194173824159216f; // 1/sqrt(512)

    const float* qbase = g_q + ((size_t)bh * 1024 + i0 + warp * 16) * 64;
    unsigned qa[8][4];
    #pragma unroll
    for (int k = 0; k < 8; k++) {
        qa[k][0] = f2tf(qbase[(g    ) * 64 + k * 8 + t    ] * scale);
        qa[k][1] = f2tf(qbase[(g + 8) * 64 + k * 8 + t    ] * scale);
        qa[k][2] = f2tf(qbase[(g    ) * 64 + k * 8 + t + 4] * scale);
        qa[k][3] = f2tf(qbase[(g + 8) * 64 + k * 8 + t + 4] * scale);
    }

    // cp.async chunk loader: 512 16B pieces each for K and V; 2+2 per thread
    auto issue_load = [&](int ch) {
        int bufi = ch & 1;
        unsigned Kb = smem_u32 + (KS_OFF + bufi * 32 * KSTRIDE) * 4;
        unsigned Vb = smem_u32 + (VS_OFF + bufi * 32 * VSTRIDE) * 4;
        #pragma unroll
        for (int it = 0; it < 2; it++) {
            int i = tid + it * 256;        // 0..511
            int key = i >> 4;
            int dc = (i & 15) << 2;        // d base (4 floats)
            int gkey = ch * 32 + key;
            int sz = (gkey < nk) ? 16 : 0;
            cp16(Kb + (key * KSTRIDE + dc) * 4, kbase + (size_t)gkey * 64 + dc, sz);
            cp16(Vb + (key * VSTRIDE + dc) * 4, vbase + (size_t)gkey * 64 + dc, sz);
        }
        asm volatile("cp.async.commit_group;\n");
    };

    float oacc[8][4];
    #pragma unroll
    for (int n = 0; n < 8; n++)
        #pragma unroll
        for (int j = 0; j < 4; j++) oacc[n][j] = 0.f;
    float mrow0 = -1e30f, mrow1 = -1e30f;
    float lrow0 = 0.f,    lrow1 = 0.f;

    unsigned* Pw = sm + PS_OFF + warp * 768;   // PsT[32][24]

    issue_load(0);

    for (int ch = 0; ch < nchunks; ch++) {
        const int cur = ch & 1;
        if (ch + 1 < nchunks) {
            issue_load(ch + 1);
            asm volatile("cp.async.wait_group 1;\n");
        } else {
            asm volatile("cp.async.wait_group 0;\n");
        }
        __syncthreads();

        const unsigned* Kb = sm + KS_OFF + cur * 32 * KSTRIDE;
        const unsigned* Vb = sm + VS_OFF + cur * 32 * VSTRIDE;
        const int j0 = ch * 32;

        // S = (Q*scale) @ K^T  -- K natural [key][d], stride 68 (bank 4g+t)
        float sc[4][4];
        #pragma unroll
        for (int n = 0; n < 4; n++)
            #pragma unroll
            for (int j = 0; j < 4; j++) sc[n][j] = 0.f;
        #pragma unroll
        for (int k = 0; k < 8; k++) {
            #pragma unroll
            for (int n = 0; n < 4; n++) {
                unsigned b0 = Kb[(n * 8 + g) * KSTRIDE + k * 8 + t    ];
                unsigned b1 = Kb[(n * 8 + g) * KSTRIDE + k * 8 + t + 4];
                mma_tf32(sc[n], qa[k][0], qa[k][1], qa[k][2], qa[k][3], b0, b1);
            }
        }

        float mx0 = -1e30f, mx1 = -1e30f;
        #pragma unroll
        for (int n = 0; n < 4; n++) {
            int c0 = j0 + n * 8 + 2 * t;
            bool ok0 = c0 < nk, ok1 = (c0 + 1) < nk;
            float v0 = ok0 ? sc[n][0] : -10000.0f;
            float v1 = ok1 ? sc[n][1] : -10000.0f;
            float v2 = ok0 ? sc[n][2] : -10000.0f;
            float v3 = ok1 ? sc[n][3] : -10000.0f;
            sc[n][0] = v0; sc[n][1] = v1; sc[n][2] = v2; sc[n][3] = v3;
            mx0 = fmaxf(mx0, fmaxf(v0, v1));
            mx1 = fmaxf(mx1, fmaxf(v2, v3));
        }
        mx0 = fmaxf(mx0, __shfl_xor_sync(0xffffffffu, mx0, 1));
        mx0 = fmaxf(mx0, __shfl_xor_sync(0xffffffffu, mx0, 2));
        mx1 = fmaxf(mx1, __shfl_xor_sync(0xffffffffu, mx1, 1));
        mx1 = fmaxf(mx1, __shfl_xor_sync(0xffffffffu, mx1, 2));

        float mn0 = fmaxf(mrow0, mx0), mn1 = fmaxf(mrow1, mx1);
        float f0 = __expf(mrow0 - mn0), f1 = __expf(mrow1 - mn1);
        float s0 = 0.f, s1 = 0.f;
        #pragma unroll
        for (int n = 0; n < 4; n++) {
            float p0 = __expf(sc[n][0] - mn0);
            float p1 = __expf(sc[n][1] - mn0);
            float p2 = __expf(sc[n][2] - mn1);
            float p3 = __expf(sc[n][3] - mn1);
            s0 += p0 + p1; s1 += p2 + p3;
            Pw[(n * 8 + 2 * t    ) * 24 + g    ] = f2tf(p0);
            Pw[(n * 8 + 2 * t + 1) * 24 + g    ] = f2tf(p1);
            Pw[(n * 8 + 2 * t    ) * 24 + g + 8] = f2tf(p2);
            Pw[(n * 8 + 2 * t + 1) * 24 + g + 8] = f2tf(p3);
        }
        s0 += __shfl_xor_sync(0xffffffffu, s0, 1);
        s0 += __shfl_xor_sync(0xffffffffu, s0, 2);
        s1 += __shfl_xor_sync(0xffffffffu, s1, 1);
        s1 += __shfl_xor_sync(0xffffffffu, s1, 2);

        lrow0 = lrow0 * f0 + s0;
        lrow1 = lrow1 * f1 + s1;
        mrow0 = mn0; mrow1 = mn1;
        #pragma unroll
        for (int n = 0; n < 8; n++) {
            oacc[n][0] *= f0; oacc[n][1] *= f0;
            oacc[n][2] *= f1; oacc[n][3] *= f1;
        }
        __syncwarp();

        // O += P @ V  -- V natural [key][d], stride 72 (bank 8t+g)
        #pragma unroll
        for (int k = 0; k < 4; k++) {
            unsigned a0 = Pw[(k * 8 + t    ) * 24 + g    ];
            unsigned a1 = Pw[(k * 8 + t    ) * 24 + g + 8];
            unsigned a2 = Pw[(k * 8 + t + 4) * 24 + g    ];
            unsigned a3 = Pw[(k * 8 + t + 4) * 24 + g + 8];
            #pragma unroll
            for (int n = 0; n < 8; n++) {
                unsigned b0 = Vb[(k * 8 + t    ) * VSTRIDE + n * 8 + g];
                unsigned b1 = Vb[(k * 8 + t + 4) * VSTRIDE + n * 8 + g];
                mma_tf32(oacc[n], a0, a1, a2, a3, b0, b1);
            }
        }
        __syncthreads();   // all warps done with buffer `cur` before reload
    }

    float r0 = 1.0f / lrow0, r1 = 1.0f / lrow1;
    int row0 = i0 + warp * 16 + g;
    int row1 = row0 + 8;
    float* o0 = g_O + ((size_t)(b * 1024 + row0)) * 512 + h * 64;
    float* o1 = g_O + ((size_t)(b * 1024 + row1)) * 512 + h * 64;
    #pragma unroll
    for (int n = 0; n < 8; n++) {
        int d = n * 8 + 2 * t;
        o0[d    ] = oacc[n][0] * r0 + qbase[(g    ) * 64 + d    ];
        o0[d + 1] = oacc[n][1] * r0 + qbase[(g    ) * 64 + d + 1];
        o1[d    ] = oacc[n][2] * r1 + qbase[(g + 8) * 64 + d    ];
        o1[d + 1] = oacc[n][3] * r1 + qbase[(g + 8) * 64 + d + 1];
    }
}

// ---------------- LN0 row stats over g_O ------------------------------------
__global__ void ln_stats()
{
    __shared__ float red[4];
    const int row = blockIdx.x, t = threadIdx.x;
    const float* p = g_O + (size_t)row * 512;
    float v[4];
    #pragma unroll
    for (int i = 0; i < 4; i++) v[i] = p[t + 128 * i];

    float s = v[0] + v[1] + v[2] + v[3];
    s = warpSum(s);
    if ((t & 31) == 0) red[t >> 5] = s;
    __syncthreads();
    s = red[0] + red[1] + red[2] + red[3];
    float mean = s * (1.f / 512.f);
    __syncthreads();

    float ss = 0.f;
    #pragma unroll
    for (int i = 0; i < 4; i++) { float d = v[i] - mean; ss += d * d; }
    ss = warpSum(ss);
    if ((t & 31) == 0) red[t >> 5] = ss;
    __syncthreads();
    ss = red[0] + red[1] + red[2] + red[3];
    if (t == 0) {
        g_mu[row] = mean;
        g_rs[row] = rsqrtf(ss * (1.f / 512.f) + 1e-5f);
    }
}

// ---------------- final LayerNorm: g_U -> out --------------------------------
__global__ void ln_final(const float* __restrict__ gg, const float* __restrict__ bb,
                         float* __restrict__ out)
{
    __shared__ float red[4];
    const int row = blockIdx.x, t = threadIdx.x;
    const float* p = g_U + (size_t)row * 512;
    float v[4];
    #pragma unroll
    for (int i = 0; i < 4; i++) v[i] = p[t + 128 * i];

    float s = v[0] + v[1] + v[2] + v[3];
    s = warpSum(s);
    if ((t & 31) == 0) red[t >> 5] = s;
    __syncthreads();
    s = red[0] + red[1] + red[2] + red[3];
    float mean = s * (1.f / 512.f);
    __syncthreads();

    float ss = 0.f;
    #pragma unroll
    for (int i = 0; i < 4; i++) { float d = v[i] - mean; ss += d * d; }
    ss = warpSum(ss);
    if ((t & 31) == 0) red[t >> 5] = ss;
    __syncthreads();
    ss = red[0] + red[1] + red[2] + red[3];
    float inv = rsqrtf(ss * (1.f / 512.f) + 1e-5f);

    #pragma unroll
    for (int i = 0; i < 4; i++) {
        int c = t + 128 * i;
        out[(size_t)row * 512 + c] = (v[i] - mean) * inv * gg[c] + bb[c];
    }
}

// ---------------- launch ----------------------------------------------------
extern "C" void kernel_launch(void* const* d_in, const int* in_sizes, int n_in,
                              void* d_out, int out_size)
{
    const float* Q    = (const float*)d_in[0];
    const float* K    = (const float*)d_in[1];
    const int*   mask = (const int*)  d_in[2];
    const float* Wq   = (const float*)d_in[3];
    const float* bq   = (const float*)d_in[4];
    const float* Wk   = (const float*)d_in[5];
    const float* bk   = (const float*)d_in[6];
    const float* Wv   = (const float*)d_in[7];
    const float* bv   = (const float*)d_in[8];
    const float* Wo   = (const float*)d_in[9];
    const float* bo   = (const float*)d_in[10];
    const float* g0   = (const float*)d_in[11];
    const float* b0   = (const float*)d_in[12];
    const float* g1   = (const float*)d_in[13];
    const float* b1   = (const float*)d_in[14];
    float* out = (float*)d_out;

    static bool attr_set = false;
    if (!attr_set) {
        cudaFuncSetAttribute(flash_attn, cudaFuncAttributeMaxDynamicSharedMemorySize,
                             SMEM_FLASH);
        attr_set = true;
    }

    compact_mask<<<BATCH, 1024>>>(mask);

    dim3 gqkv(DIM / 128, MROWS / 128, 3);   // (4, 64, 3)
    gemm128<0><<<gqkv, 256>>>(Q, K, Wq, bq, Wk, bk, Wv, bv);

    dim3 gf(NQ / 128, BH);                  // (8, 64)
    flash_attn<<<gf, 256, SMEM_FLASH>>>();

    ln_stats<<<MROWS, 128>>>();

    dim3 go(DIM / 128, MROWS / 128, 1);     // (4, 64)
    gemm128<1><<<go, 256>>>(nullptr, nullptr, Wo, bo, g0, b0, nullptr, nullptr);

    ln_final<<<MROWS, 128>>>(g1, b1, out);
}

// round 9
// speedup vs baseline: 5.5492x; 1.0164x over previous
#include <cuda_runtime.h>
#include <math.h>

// Problem constants: B=8, NQ=NK=1024, D=512, H=8, dh=64
#define BATCH 8
#define NQ 1024
#define NK 1024
#define DIM 512
#define HEADS 8
#define DH 64
#define BH (BATCH*HEADS)          // 64
#define MROWS (BATCH*NQ)          // 8192

// ---------------- scratch ----------------
__device__ float g_q[BH * NK * DH];   // full rows, f32
__device__ float g_k[BH * NK * DH];   // COMPACTED rows, tf32-rounded
__device__ float g_v[BH * NK * DH];   // COMPACTED rows, tf32-rounded
__device__ float g_O[MROWS * DIM];
__device__ float g_U[MROWS * DIM];
__device__ float g_mu[MROWS];
__device__ float g_rs[MROWS];
__device__ int   g_idx[BATCH * NK];
__device__ int   g_cnt[BATCH];

// ---------------- helpers ----------------
__device__ __forceinline__ float warpSum(float v) {
    #pragma unroll
    for (int o = 16; o > 0; o >>= 1) v += __shfl_xor_sync(0xffffffffu, v, o);
    return v;
}

__device__ __forceinline__ unsigned f2tf(float x) {
    unsigned u;
    asm("cvt.rna.tf32.f32 %0, %1;" : "=r"(u) : "f"(x));
    return u;
}

__device__ __forceinline__ void mma_tf32(float c[4],
                                         unsigned a0, unsigned a1, unsigned a2, unsigned a3,
                                         unsigned b0, unsigned b1)
{
    asm volatile(
        "mma.sync.aligned.m16n8k8.row.col.f32.tf32.tf32.f32 "
        "{%0,%1,%2,%3}, {%4,%5,%6,%7}, {%8,%9}, {%0,%1,%2,%3};\n"
        : "+f"(c[0]), "+f"(c[1]), "+f"(c[2]), "+f"(c[3])
        : "r"(a0), "r"(a1), "r"(a2), "r"(a3), "r"(b0), "r"(b1));
}

__device__ __forceinline__ void cp16(unsigned smem_addr, const void* gptr, int src_sz) {
    asm volatile("cp.async.cg.shared.global [%0], [%1], 16, %2;\n"
                 :: "r"(smem_addr), "l"(gptr), "r"(src_sz));
}
__device__ __forceinline__ void cp16f(unsigned smem_addr, const void* gptr) {
    asm volatile("cp.async.cg.shared.global [%0], [%1], 16;\n"
                 :: "r"(smem_addr), "l"(gptr));
}

__device__ __forceinline__ unsigned smem_cast(const void* p) {
    unsigned long long q;
    asm("cvta.to.shared.u64 %0, %1;" : "=l"(q) : "l"(p));
    return (unsigned)q;
}

// ---------------- mask compaction ----------------
__global__ void compact_mask(const int* __restrict__ mask)
{
    __shared__ int warpsums[32];
    const int b = blockIdx.x, t = threadIdx.x;
    const int lane = t & 31, warp = t >> 5;
    int m = (mask[b * 1024 + t] != 0) ? 1 : 0;
    unsigned bal = __ballot_sync(0xffffffffu, m);
    int pre = __popc(bal & ((1u << lane) - 1u));
    if (lane == 0) warpsums[warp] = __popc(bal);
    __syncthreads();
    if (warp == 0) {
        int v = warpsums[lane];
        #pragma unroll
        for (int o = 1; o < 32; o <<= 1) {
            int u = __shfl_up_sync(0xffffffffu, v, o);
            if (lane >= o) v += u;
        }
        warpsums[lane] = v;
    }
    __syncthreads();
    int base = (warp == 0) ? 0 : warpsums[warp - 1];
    if (m) g_idx[b * 1024 + base + pre] = t;
    if (t == 1023) g_cnt[b] = warpsums[31];
}

// ---------------- 128x128 tensor-core GEMM (cp.async, natural A) -----------
// MODE 0 (grid.z=3): z=0: Q@Wq+bq -> g_q ; z=1/2: K@{Wk,Wv}+b -> g_k/g_v
// MODE 1 (grid.z=1): A = LN0(g_O) on the fly; g_U = LN0(g_O) + relu(A@W+bias)
#define ASTRIDE 20     // 20 ≡ 20 mod 32; a-frag banks 20g+t distinct
#define BSTRIDE 132    // 132 ≡ 4 mod 32; b-frag banks 4t+g distinct
template<int MODE>
__global__ void __launch_bounds__(256, 2) gemm128(
    const float* __restrict__ p0, const float* __restrict__ p1,
    const float* __restrict__ p2, const float* __restrict__ p3,
    const float* __restrict__ p4, const float* __restrict__ p5,
    const float* __restrict__ p6, const float* __restrict__ p7)
{
    __shared__ float As[2][128][ASTRIDE];   // natural [m][k], raw f32
    __shared__ float Bs[2][16][BSTRIDE];    // [k][n], raw f32
    const int z = blockIdx.z;
    const int n0 = blockIdx.x * 128;
    const int bb = blockIdx.y >> 3;
    const int tyl = blockIdx.y & 7;
    const int m0 = blockIdx.y * 128;

    const float* A; const float* W; const float* bias; float* outp;
    const float* gamma = p4; const float* beta = p5;
    if (MODE == 0) {
        A    = (z == 0) ? p0 : p1;
        W    = (z == 0) ? p2 : (z == 1) ? p4 : p6;
        bias = (z == 0) ? p3 : (z == 1) ? p5 : p7;
        outp = (z == 0) ? g_q : (z == 1) ? g_k : g_v;
    } else {
        A = (const float*)g_O; W = p2; bias = p3; outp = g_U;
    }

    int cnt = 1024;
    if (MODE == 0 && z > 0) {
        cnt = g_cnt[bb];
        if (tyl * 128 >= cnt) return;
    }

    const int tid = threadIdx.x;
    const int warp = tid >> 5, lane = tid & 31;
    const int wm = warp >> 2, wn = warp & 3;
    const int g = lane >> 2, t = lane & 3;
    const int mbase = wm * 64;
    const int nbase = wn * 32;

    const unsigned sA = smem_cast(As);
    const unsigned sB = smem_cast(Bs);

    const int r1 = tid >> 2;            // A row (and row+64)
    const int c4 = (tid & 3) << 2;      // k sub-offset (4 floats)
    const float* arow1; const float* arow2;
    float mu1 = 0.f, rs1 = 0.f, mu2 = 0.f, rs2 = 0.f;
    {
        int li1 = tyl * 128 + r1;
        int li2 = li1 + 64;
        if (MODE == 0 && z > 0) {
            int gi1 = (li1 < cnt) ? g_idx[bb * 1024 + li1] : 0;
            int gi2 = (li2 < cnt) ? g_idx[bb * 1024 + li2] : 0;
            arow1 = A + ((size_t)bb * 1024 + gi1) * 512;
            arow2 = A + ((size_t)bb * 1024 + gi2) * 512;
        } else {
            arow1 = A + ((size_t)bb * 1024 + li1) * 512;
            arow2 = A + ((size_t)bb * 1024 + li2) * 512;
        }
        if (MODE == 1) {
            mu1 = g_mu[m0 + r1];      rs1 = g_rs[m0 + r1];
            mu2 = g_mu[m0 + r1 + 64]; rs2 = g_rs[m0 + r1 + 64];
        }
    }

    auto loadAB = [&](int k0, int bufi) {
        unsigned abase = sA + (unsigned)(bufi * 128 * ASTRIDE) * 4;
        if (MODE == 0) {
            cp16f(abase + (unsigned)((r1      ) * ASTRIDE + c4) * 4, arow1 + k0 + c4);
            cp16f(abase + (unsigned)((r1 + 64 ) * ASTRIDE + c4) * 4, arow2 + k0 + c4);
        } else {
            float4 a1 = *(const float4*)(arow1 + k0 + c4);
            float4 a2 = *(const float4*)(arow2 + k0 + c4);
            float4 gm = *(const float4*)(gamma + k0 + c4);
            float4 bt = *(const float4*)(beta  + k0 + c4);
            a1.x = (a1.x - mu1) * rs1 * gm.x + bt.x;
            a1.y = (a1.y - mu1) * rs1 * gm.y + bt.y;
            a1.z = (a1.z - mu1) * rs1 * gm.z + bt.z;
            a1.w = (a1.w - mu1) * rs1 * gm.w + bt.w;
            a2.x = (a2.x - mu2) * rs2 * gm.x + bt.x;
            a2.y = (a2.y - mu2) * rs2 * gm.y + bt.y;
            a2.z = (a2.z - mu2) * rs2 * gm.z + bt.z;
            a2.w = (a2.w - mu2) * rs2 * gm.w + bt.w;
            // RNA-round the normalized activations (cheap, register-side)
            uint4 u1 = make_uint4(f2tf(a1.x), f2tf(a1.y), f2tf(a1.z), f2tf(a1.w));
            uint4 u2 = make_uint4(f2tf(a2.x), f2tf(a2.y), f2tf(a2.z), f2tf(a2.w));
            *(uint4*)&As[bufi][r1     ][c4] = u1;
            *(uint4*)&As[bufi][r1 + 64][c4] = u2;
        }
        unsigned bbase = sB + (unsigned)(bufi * 16 * BSTRIDE) * 4;
        #pragma unroll
        for (int it = 0; it < 2; it++) {
            int idx = tid + it * 256;
            int r = idx >> 5, cc = (idx & 31) << 2;
            cp16f(bbase + (unsigned)(r * BSTRIDE + cc) * 4,
                  W + (size_t)(k0 + r) * 512 + n0 + cc);
        }
        asm volatile("cp.async.commit_group;\n");
    };

    float acc[4][4][4];
    #pragma unroll
    for (int i = 0; i < 4; i++)
        #pragma unroll
        for (int j = 0; j < 4; j++)
            #pragma unroll
            for (int q = 0; q < 4; q++) acc[i][j][q] = 0.f;

    loadAB(0, 0);

    for (int it = 0; it < 32; it++) {
        int cur = it & 1;
        if (it < 31) {
            loadAB((it + 1) * 16, cur ^ 1);
            asm volatile("cp.async.wait_group 1;\n");
        } else {
            asm volatile("cp.async.wait_group 0;\n");
        }
        __syncthreads();

        const unsigned* Ab = (const unsigned*)As[cur];
        const unsigned* Bb = (const unsigned*)Bs[cur];
        #pragma unroll
        for (int ks = 0; ks < 2; ks++) {
            int kk = ks * 8;
            unsigned av[4][4], bv[4][2];
            #pragma unroll
            for (int i = 0; i < 4; i++) {
                int mb = mbase + i * 16;
                av[i][0] = Ab[(mb + g    ) * ASTRIDE + kk + t    ];
                av[i][1] = Ab[(mb + g + 8) * ASTRIDE + kk + t    ];
                av[i][2] = Ab[(mb + g    ) * ASTRIDE + kk + t + 4];
                av[i][3] = Ab[(mb + g + 8) * ASTRIDE + kk + t + 4];
            }
            #pragma unroll
            for (int j = 0; j < 4; j++) {
                bv[j][0] = Bb[(kk + t    ) * BSTRIDE + nbase + j * 8 + g];
                bv[j][1] = Bb[(kk + t + 4) * BSTRIDE + nbase + j * 8 + g];
            }
            #pragma unroll
            for (int i = 0; i < 4; i++)
                #pragma unroll
                for (int j = 0; j < 4; j++)
                    mma_tf32(acc[i][j], av[i][0], av[i][1], av[i][2], av[i][3],
                             bv[j][0], bv[j][1]);
        }
        __syncthreads();   // all reads of buffer `cur` done before it is rewritten
    }

    #pragma unroll
    for (int i = 0; i < 4; i++) {
        int lr0 = mbase + i * 16 + g;
        #pragma unroll
        for (int j = 0; j < 4; j++) {
            int c0 = n0 + nbase + j * 8 + 2 * t;
            #pragma unroll
            for (int q = 0; q < 4; q++) {
                int lr = lr0 + (q >> 1) * 8;
                int c  = c0 + (q & 1);
                float val = acc[i][j][q] + bias[c];
                if (MODE == 0) {
                    int n = tyl * 128 + lr;
                    int h = c >> 6, d = c & 63;
                    float sval = (z == 0) ? val : __uint_as_float(f2tf(val));
                    outp[(((size_t)(bb * HEADS + h)) * 1024 + n) * 64 + d] = sval;
                } else {
                    int r = m0 + lr;
                    float xv = (g_O[(size_t)r * 512 + c] - g_mu[r]) * g_rs[r]
                               * gamma[c] + beta[c];
                    outp[(size_t)r * 512 + c] = xv + fmaxf(val, 0.f);
                }
            }
        }
    }
}

// ---------------- fused flash attention (cp.async, natural layouts) --------
#define KSTRIDE 68
#define VSTRIDE 72
#define KS_OFF 0
#define VS_OFF (2*32*KSTRIDE)
#define PS_OFF (VS_OFF + 2*32*VSTRIDE)
#define SMEM_FLASH ((PS_OFF + 8*32*24) * 4)

__global__ void __launch_bounds__(256) flash_attn()
{
    extern __shared__ unsigned sm[];
    const unsigned smem_u32 = smem_cast(sm);

    const int bh = blockIdx.y;
    const int b = bh >> 3, h = bh & 7;
    const int i0 = blockIdx.x * 128;
    const int tid = threadIdx.x;
    const int warp = tid >> 5, lane = tid & 31;
    const int g = lane >> 2, t = lane & 3;

    const int nk = g_cnt[b];
    const int nchunks = (nk + 31) >> 5;
    const float* kbase = g_k + (size_t)bh * 1024 * 64;
    const float* vbase = g_v + (size_t)bh * 1024 * 64;
    const float scale = 0.044194173824159216f; // 1/sqrt(512)

    const float* qbase = g_q + ((size_t)bh * 1024 + i0 + warp * 16) * 64;
    unsigned qa[8][4];
    #pragma unroll
    for (int k = 0; k < 8; k++) {
        qa[k][0] = f2tf(qbase[(g    ) * 64 + k * 8 + t    ] * scale);
        qa[k][1] = f2tf(qbase[(g + 8) * 64 + k * 8 + t    ] * scale);
        qa[k][2] = f2tf(qbase[(g    ) * 64 + k * 8 + t + 4] * scale);
        qa[k][3] = f2tf(qbase[(g + 8) * 64 + k * 8 + t + 4] * scale);
    }

    auto issue_load = [&](int ch) {
        int bufi = ch & 1;
        unsigned Kb = smem_u32 + (KS_OFF + bufi * 32 * KSTRIDE) * 4;
        unsigned Vb = smem_u32 + (VS_OFF + bufi * 32 * VSTRIDE) * 4;
        #pragma unroll
        for (int it = 0; it < 2; it++) {
            int i = tid + it * 256;
            int key = i >> 4;
            int dc = (i & 15) << 2;
            int gkey = ch * 32 + key;
            int sz = (gkey < nk) ? 16 : 0;
            cp16(Kb + (key * KSTRIDE + dc) * 4, kbase + (size_t)gkey * 64 + dc, sz);
            cp16(Vb + (key * VSTRIDE + dc) * 4, vbase + (size_t)gkey * 64 + dc, sz);
        }
        asm volatile("cp.async.commit_group;\n");
    };

    float oacc[8][4];
    #pragma unroll
    for (int n = 0; n < 8; n++)
        #pragma unroll
        for (int j = 0; j < 4; j++) oacc[n][j] = 0.f;
    float mrow0 = -1e30f, mrow1 = -1e30f;
    float lrow0 = 0.f,    lrow1 = 0.f;

    unsigned* Pw = sm + PS_OFF + warp * 768;

    issue_load(0);

    for (int ch = 0; ch < nchunks; ch++) {
        const int cur = ch & 1;
        if (ch + 1 < nchunks) {
            issue_load(ch + 1);
            asm volatile("cp.async.wait_group 1;\n");
        } else {
            asm volatile("cp.async.wait_group 0;\n");
        }
        __syncthreads();

        const unsigned* Kb = sm + KS_OFF + cur * 32 * KSTRIDE;
        const unsigned* Vb = sm + VS_OFF + cur * 32 * VSTRIDE;
        const int j0 = ch * 32;

        float sc[4][4];
        #pragma unroll
        for (int n = 0; n < 4; n++)
            #pragma unroll
            for (int j = 0; j < 4; j++) sc[n][j] = 0.f;
        #pragma unroll
        for (int k = 0; k < 8; k++) {
            #pragma unroll
            for (int n = 0; n < 4; n++) {
                unsigned b0 = Kb[(n * 8 + g) * KSTRIDE + k * 8 + t    ];
                unsigned b1 = Kb[(n * 8 + g) * KSTRIDE + k * 8 + t + 4];
                mma_tf32(sc[n], qa[k][0], qa[k][1], qa[k][2], qa[k][3], b0, b1);
            }
        }

        float mx0 = -1e30f, mx1 = -1e30f;
        #pragma unroll
        for (int n = 0; n < 4; n++) {
            int c0 = j0 + n * 8 + 2 * t;
            bool ok0 = c0 < nk, ok1 = (c0 + 1) < nk;
            float v0 = ok0 ? sc[n][0] : -10000.0f;
            float v1 = ok1 ? sc[n][1] : -10000.0f;
            float v2 = ok0 ? sc[n][2] : -10000.0f;
            float v3 = ok1 ? sc[n][3] : -10000.0f;
            sc[n][0] = v0; sc[n][1] = v1; sc[n][2] = v2; sc[n][3] = v3;
            mx0 = fmaxf(mx0, fmaxf(v0, v1));
            mx1 = fmaxf(mx1, fmaxf(v2, v3));
        }
        mx0 = fmaxf(mx0, __shfl_xor_sync(0xffffffffu, mx0, 1));
        mx0 = fmaxf(mx0, __shfl_xor_sync(0xffffffffu, mx0, 2));
        mx1 = fmaxf(mx1, __shfl_xor_sync(0xffffffffu, mx1, 1));
        mx1 = fmaxf(mx1, __shfl_xor_sync(0xffffffffu, mx1, 2));

        float mn0 = fmaxf(mrow0, mx0), mn1 = fmaxf(mrow1, mx1);
        float f0 = __expf(mrow0 - mn0), f1 = __expf(mrow1 - mn1);
        float s0 = 0.f, s1 = 0.f;
        #pragma unroll
        for (int n = 0; n < 4; n++) {
            float p0 = __expf(sc[n][0] - mn0);
            float p1 = __expf(sc[n][1] - mn0);
            float p2 = __expf(sc[n][2] - mn1);
            float p3 = __expf(sc[n][3] - mn1);
            s0 += p0 + p1; s1 += p2 + p3;
            Pw[(n * 8 + 2 * t    ) * 24 + g    ] = __float_as_uint(p0);
            Pw[(n * 8 + 2 * t + 1) * 24 + g    ] = __float_as_uint(p1);
            Pw[(n * 8 + 2 * t    ) * 24 + g + 8] = __float_as_uint(p2);
            Pw[(n * 8 + 2 * t + 1) * 24 + g + 8] = __float_as_uint(p3);
        }
        s0 += __shfl_xor_sync(0xffffffffu, s0, 1);
        s0 += __shfl_xor_sync(0xffffffffu, s0, 2);
        s1 += __shfl_xor_sync(0xffffffffu, s1, 1);
        s1 += __shfl_xor_sync(0xffffffffu, s1, 2);

        lrow0 = lrow0 * f0 + s0;
        lrow1 = lrow1 * f1 + s1;
        mrow0 = mn0; mrow1 = mn1;
        #pragma unroll
        for (int n = 0; n < 8; n++) {
            oacc[n][0] *= f0; oacc[n][1] *= f0;
            oacc[n][2] *= f1; oacc[n][3] *= f1;
        }
        __syncwarp();

        #pragma unroll
        for (int k = 0; k < 4; k++) {
            unsigned a0 = Pw[(k * 8 + t    ) * 24 + g    ];
            unsigned a1 = Pw[(k * 8 + t    ) * 24 + g + 8];
            unsigned a2 = Pw[(k * 8 + t + 4) * 24 + g    ];
            unsigned a3 = Pw[(k * 8 + t + 4) * 24 + g + 8];
            #pragma unroll
            for (int n = 0; n < 8; n++) {
                unsigned b0 = Vb[(k * 8 + t    ) * VSTRIDE + n * 8 + g];
                unsigned b1 = Vb[(k * 8 + t + 4) * VSTRIDE + n * 8 + g];
                mma_tf32(oacc[n], a0, a1, a2, a3, b0, b1);
            }
        }
        __syncthreads();
    }

    float r0 = 1.0f / lrow0, r1 = 1.0f / lrow1;
    int row0 = i0 + warp * 16 + g;
    int row1 = row0 + 8;
    float* o0 = g_O + ((size_t)(b * 1024 + row0)) * 512 + h * 64;
    float* o1 = g_O + ((size_t)(b * 1024 + row1)) * 512 + h * 64;
    #pragma unroll
    for (int n = 0; n < 8; n++) {
        int d = n * 8 + 2 * t;
        o0[d    ] = oacc[n][0] * r0 + qbase[(g    ) * 64 + d    ];
        o0[d + 1] = oacc[n][1] * r0 + qbase[(g    ) * 64 + d + 1];
        o1[d    ] = oacc[n][2] * r1 + qbase[(g + 8) * 64 + d    ];
        o1[d + 1] = oacc[n][3] * r1 + qbase[(g + 8) * 64 + d + 1];
    }
}

// ---------------- LN0 row stats over g_O ------------------------------------
__global__ void ln_stats()
{
    __shared__ float red[4];
    const int row = blockIdx.x, t = threadIdx.x;
    const float* p = g_O + (size_t)row * 512;
    float v[4];
    #pragma unroll
    for (int i = 0; i < 4; i++) v[i] = p[t + 128 * i];

    float s = v[0] + v[1] + v[2] + v[3];
    s = warpSum(s);
    if ((t & 31) == 0) red[t >> 5] = s;
    __syncthreads();
    s = red[0] + red[1] + red[2] + red[3];
    float mean = s * (1.f / 512.f);
    __syncthreads();

    float ss = 0.f;
    #pragma unroll
    for (int i = 0; i < 4; i++) { float d = v[i] - mean; ss += d * d; }
    ss = warpSum(ss);
    if ((t & 31) == 0) red[t >> 5] = ss;
    __syncthreads();
    ss = red[0] + red[1] + red[2] + red[3];
    if (t == 0) {
        g_mu[row] = mean;
        g_rs[row] = rsqrtf(ss * (1.f / 512.f) + 1e-5f);
    }
}

// ---------------- final LayerNorm: g_U -> out --------------------------------
__global__ void ln_final(const float* __restrict__ gg, const float* __restrict__ bb,
                         float* __restrict__ out)
{
    __shared__ float red[4];
    const int row = blockIdx.x, t = threadIdx.x;
    const float* p = g_U + (size_t)row * 512;
    float v[4];
    #pragma unroll
    for (int i = 0; i < 4; i++) v[i] = p[t + 128 * i];

    float s = v[0] + v[1] + v[2] + v[3];
    s = warpSum(s);
    if ((t & 31) == 0) red[t >> 5] = s;
    __syncthreads();
    s = red[0] + red[1] + red[2] + red[3];
    float mean = s * (1.f / 512.f);
    __syncthreads();

    float ss = 0.f;
    #pragma unroll
    for (int i = 0; i < 4; i++) { float d = v[i] - mean; ss += d * d; }
    ss = warpSum(ss);
    if ((t & 31) == 0) red[t >> 5] = ss;
    __syncthreads();
    ss = red[0] + red[1] + red[2] + red[3];
    float inv = rsqrtf(ss * (1.f / 512.f) + 1e-5f);

    #pragma unroll
    for (int i = 0; i < 4; i++) {
        int c = t + 128 * i;
        out[(size_t)row * 512 + c] = (v[i] - mean) * inv * gg[c] + bb[c];
    }
}

// ---------------- launch ----------------------------------------------------
extern "C" void kernel_launch(void* const* d_in, const int* in_sizes, int n_in,
                              void* d_out, int out_size)
{
    const float* Q    = (const float*)d_in[0];
    const float* K    = (const float*)d_in[1];
    const int*   mask = (const int*)  d_in[2];
    const float* Wq   = (const float*)d_in[3];
    const float* bq   = (const float*)d_in[4];
    const float* Wk   = (const float*)d_in[5];
    const float* bk   = (const float*)d_in[6];
    const float* Wv   = (const float*)d_in[7];
    const float* bv   = (const float*)d_in[8];
    const float* Wo   = (const float*)d_in[9];
    const float* bo   = (const float*)d_in[10];
    const float* g0   = (const float*)d_in[11];
    const float* b0   = (const float*)d_in[12];
    const float* g1   = (const float*)d_in[13];
    const float* b1   = (const float*)d_in[14];
    float* out = (float*)d_out;

    static bool attr_set = false;
    if (!attr_set) {
        cudaFuncSetAttribute(flash_attn, cudaFuncAttributeMaxDynamicSharedMemorySize,
                             SMEM_FLASH);
        attr_set = true;
    }

    compact_mask<<<BATCH, 1024>>>(mask);

    dim3 gqkv(DIM / 128, MROWS / 128, 3);   // (4, 64, 3)
    gemm128<0><<<gqkv, 256>>>(Q, K, Wq, bq, Wk, bk, Wv, bv);

    dim3 gf(NQ / 128, BH);                  // (8, 64)
    flash_attn<<<gf, 256, SMEM_FLASH>>>();

    ln_stats<<<MROWS, 128>>>();

    dim3 go(DIM / 128, MROWS / 128, 1);     // (4, 64)
    gemm128<1><<<go, 256>>>(nullptr, nullptr, Wo, bo, g0, b0, nullptr, nullptr);

    ln_final<<<MROWS, 128>>>(g1, b1, out);
}

// round 10
// speedup vs baseline: 5.8620x; 1.0564x over previous
#include <cuda_runtime.h>
#include <math.h>

// Problem constants: B=8, NQ=NK=1024, D=512, H=8, dh=64
#define BATCH 8
#define NQ 1024
#define NK 1024
#define DIM 512
#define HEADS 8
#define DH 64
#define BH (BATCH*HEADS)          // 64
#define MROWS (BATCH*NQ)          // 8192

// ---------------- scratch ----------------
__device__ float g_q[BH * NK * DH];   // full rows, f32
__device__ float g_k[BH * NK * DH];   // COMPACTED rows, tf32-rounded
__device__ float g_v[BH * NK * DH];   // COMPACTED rows, tf32-rounded
__device__ float g_O[MROWS * DIM];
__device__ float g_U[MROWS * DIM];
__device__ float g_mu[MROWS];
__device__ float g_rs[MROWS];
__device__ float g_part[MROWS][HEADS][2];   // per (row, head) LN0 partial sums
__device__ int   g_idx[BATCH * NK];
__device__ int   g_cnt[BATCH];

// ---------------- helpers ----------------
__device__ __forceinline__ unsigned f2tf(float x) {
    unsigned u;
    asm("cvt.rna.tf32.f32 %0, %1;" : "=r"(u) : "f"(x));
    return u;
}

__device__ __forceinline__ void mma_tf32(float c[4],
                                         unsigned a0, unsigned a1, unsigned a2, unsigned a3,
                                         unsigned b0, unsigned b1)
{
    asm volatile(
        "mma.sync.aligned.m16n8k8.row.col.f32.tf32.tf32.f32 "
        "{%0,%1,%2,%3}, {%4,%5,%6,%7}, {%8,%9}, {%0,%1,%2,%3};\n"
        : "+f"(c[0]), "+f"(c[1]), "+f"(c[2]), "+f"(c[3])
        : "r"(a0), "r"(a1), "r"(a2), "r"(a3), "r"(b0), "r"(b1));
}

__device__ __forceinline__ void cp16(unsigned smem_addr, const void* gptr, int src_sz) {
    asm volatile("cp.async.cg.shared.global [%0], [%1], 16, %2;\n"
                 :: "r"(smem_addr), "l"(gptr), "r"(src_sz));
}
__device__ __forceinline__ void cp16f(unsigned smem_addr, const void* gptr) {
    asm volatile("cp.async.cg.shared.global [%0], [%1], 16;\n"
                 :: "r"(smem_addr), "l"(gptr));
}

__device__ __forceinline__ unsigned smem_cast(const void* p) {
    unsigned long long q;
    asm("cvta.to.shared.u64 %0, %1;" : "=l"(q) : "l"(p));
    return (unsigned)q;
}

// ---------------- mask compaction ----------------
__global__ void compact_mask(const int* __restrict__ mask)
{
    __shared__ int warpsums[32];
    const int b = blockIdx.x, t = threadIdx.x;
    const int lane = t & 31, warp = t >> 5;
    int m = (mask[b * 1024 + t] != 0) ? 1 : 0;
    unsigned bal = __ballot_sync(0xffffffffu, m);
    int pre = __popc(bal & ((1u << lane) - 1u));
    if (lane == 0) warpsums[warp] = __popc(bal);
    __syncthreads();
    if (warp == 0) {
        int v = warpsums[lane];
        #pragma unroll
        for (int o = 1; o < 32; o <<= 1) {
            int u = __shfl_up_sync(0xffffffffu, v, o);
            if (lane >= o) v += u;
        }
        warpsums[lane] = v;
    }
    __syncthreads();
    int base = (warp == 0) ? 0 : warpsums[warp - 1];
    if (m) g_idx[b * 1024 + base + pre] = t;
    if (t == 1023) g_cnt[b] = warpsums[31];
}

// ---------------- 128x128 tensor-core GEMM (4-stage cp.async) --------------
// MODE 0 (grid.z=3): z=0: Q@Wq+bq -> g_q ; z=1/2: K@{Wk,Wv}+b -> g_k/g_v
// MODE 1 (grid.z=1): A = LN0(g_O) on the fly; g_U = LN0(g_O) + relu(A@W+bias)
#define ASTRIDE 20
#define BSTRIDE 132
#define GSTAGES 4
#define GEMM_SMEM ((GSTAGES*128*ASTRIDE + GSTAGES*16*BSTRIDE) * 4)
template<int MODE>
__global__ void __launch_bounds__(256, 2) gemm128(
    const float* __restrict__ p0, const float* __restrict__ p1,
    const float* __restrict__ p2, const float* __restrict__ p3,
    const float* __restrict__ p4, const float* __restrict__ p5,
    const float* __restrict__ p6, const float* __restrict__ p7)
{
    extern __shared__ float smg[];
    float (*As)[128][ASTRIDE] = (float(*)[128][ASTRIDE])smg;
    float (*Bs)[16][BSTRIDE]  = (float(*)[16][BSTRIDE])(smg + GSTAGES*128*ASTRIDE);
    const int z = blockIdx.z;
    const int n0 = blockIdx.x * 128;
    const int bb = blockIdx.y >> 3;
    const int tyl = blockIdx.y & 7;
    const int m0 = blockIdx.y * 128;

    const float* A; const float* W; const float* bias; float* outp;
    const float* gamma = p4; const float* beta = p5;
    if (MODE == 0) {
        A    = (z == 0) ? p0 : p1;
        W    = (z == 0) ? p2 : (z == 1) ? p4 : p6;
        bias = (z == 0) ? p3 : (z == 1) ? p5 : p7;
        outp = (z == 0) ? g_q : (z == 1) ? g_k : g_v;
    } else {
        A = (const float*)g_O; W = p2; bias = p3; outp = g_U;
    }

    int cnt = 1024;
    if (MODE == 0 && z > 0) {
        cnt = g_cnt[bb];
        if (tyl * 128 >= cnt) return;
    }

    const int tid = threadIdx.x;
    const int warp = tid >> 5, lane = tid & 31;
    const int wm = warp >> 2, wn = warp & 3;
    const int g = lane >> 2, t = lane & 3;
    const int mbase = wm * 64;
    const int nbase = wn * 32;

    const unsigned sA = smem_cast(smg);
    const unsigned sB = sA + (unsigned)(GSTAGES*128*ASTRIDE) * 4;

    const int r1 = tid >> 2;
    const int c4 = (tid & 3) << 2;
    const float* arow1; const float* arow2;
    float mu1 = 0.f, rs1 = 0.f, mu2 = 0.f, rs2 = 0.f;
    {
        int li1 = tyl * 128 + r1;
        int li2 = li1 + 64;
        if (MODE == 0 && z > 0) {
            int gi1 = (li1 < cnt) ? g_idx[bb * 1024 + li1] : 0;
            int gi2 = (li2 < cnt) ? g_idx[bb * 1024 + li2] : 0;
            arow1 = A + ((size_t)bb * 1024 + gi1) * 512;
            arow2 = A + ((size_t)bb * 1024 + gi2) * 512;
        } else {
            arow1 = A + ((size_t)bb * 1024 + li1) * 512;
            arow2 = A + ((size_t)bb * 1024 + li2) * 512;
        }
        if (MODE == 1) {
            mu1 = g_mu[m0 + r1];      rs1 = g_rs[m0 + r1];
            mu2 = g_mu[m0 + r1 + 64]; rs2 = g_rs[m0 + r1 + 64];
        }
    }

    auto loadAB = [&](int k0, int bufi) {
        unsigned abase = sA + (unsigned)(bufi * 128 * ASTRIDE) * 4;
        if (MODE == 0) {
            cp16f(abase + (unsigned)((r1      ) * ASTRIDE + c4) * 4, arow1 + k0 + c4);
            cp16f(abase + (unsigned)((r1 + 64 ) * ASTRIDE + c4) * 4, arow2 + k0 + c4);
        } else {
            float4 a1 = *(const float4*)(arow1 + k0 + c4);
            float4 a2 = *(const float4*)(arow2 + k0 + c4);
            float4 gm = *(const float4*)(gamma + k0 + c4);
            float4 bt = *(const float4*)(beta  + k0 + c4);
            a1.x = (a1.x - mu1) * rs1 * gm.x + bt.x;
            a1.y = (a1.y - mu1) * rs1 * gm.y + bt.y;
            a1.z = (a1.z - mu1) * rs1 * gm.z + bt.z;
            a1.w = (a1.w - mu1) * rs1 * gm.w + bt.w;
            a2.x = (a2.x - mu2) * rs2 * gm.x + bt.x;
            a2.y = (a2.y - mu2) * rs2 * gm.y + bt.y;
            a2.z = (a2.z - mu2) * rs2 * gm.z + bt.z;
            a2.w = (a2.w - mu2) * rs2 * gm.w + bt.w;
            uint4 u1 = make_uint4(f2tf(a1.x), f2tf(a1.y), f2tf(a1.z), f2tf(a1.w));
            uint4 u2 = make_uint4(f2tf(a2.x), f2tf(a2.y), f2tf(a2.z), f2tf(a2.w));
            *(uint4*)&As[bufi][r1     ][c4] = u1;
            *(uint4*)&As[bufi][r1 + 64][c4] = u2;
        }
        unsigned bbase = sB + (unsigned)(bufi * 16 * BSTRIDE) * 4;
        #pragma unroll
        for (int it = 0; it < 2; it++) {
            int idx = tid + it * 256;
            int r = idx >> 5, cc = (idx & 31) << 2;
            cp16f(bbase + (unsigned)(r * BSTRIDE + cc) * 4,
                  W + (size_t)(k0 + r) * 512 + n0 + cc);
        }
        asm volatile("cp.async.commit_group;\n");
    };

    float acc[4][4][4];
    #pragma unroll
    for (int i = 0; i < 4; i++)
        #pragma unroll
        for (int j = 0; j < 4; j++)
            #pragma unroll
            for (int q = 0; q < 4; q++) acc[i][j][q] = 0.f;

    loadAB(0, 0);
    loadAB(16, 1);

    for (int it = 0; it < 32; it++) {
        int cur = it & 3;
        if (it + 2 < 32) loadAB((it + 2) * 16, (it + 2) & 3);
        else asm volatile("cp.async.commit_group;\n");
        asm volatile("cp.async.wait_group 2;\n");
        __syncthreads();

        const unsigned* Ab = (const unsigned*)As[cur];
        const unsigned* Bb = (const unsigned*)Bs[cur];
        #pragma unroll
        for (int ks = 0; ks < 2; ks++) {
            int kk = ks * 8;
            unsigned av[4][4], bv[4][2];
            #pragma unroll
            for (int i = 0; i < 4; i++) {
                int mb = mbase + i * 16;
                av[i][0] = Ab[(mb + g    ) * ASTRIDE + kk + t    ];
                av[i][1] = Ab[(mb + g + 8) * ASTRIDE + kk + t    ];
                av[i][2] = Ab[(mb + g    ) * ASTRIDE + kk + t + 4];
                av[i][3] = Ab[(mb + g + 8) * ASTRIDE + kk + t + 4];
            }
            #pragma unroll
            for (int j = 0; j < 4; j++) {
                bv[j][0] = Bb[(kk + t    ) * BSTRIDE + nbase + j * 8 + g];
                bv[j][1] = Bb[(kk + t + 4) * BSTRIDE + nbase + j * 8 + g];
            }
            #pragma unroll
            for (int i = 0; i < 4; i++)
                #pragma unroll
                for (int j = 0; j < 4; j++)
                    mma_tf32(acc[i][j], av[i][0], av[i][1], av[i][2], av[i][3],
                             bv[j][0], bv[j][1]);
        }
    }

    #pragma unroll
    for (int i = 0; i < 4; i++) {
        int lr0 = mbase + i * 16 + g;
        #pragma unroll
        for (int j = 0; j < 4; j++) {
            int c0 = n0 + nbase + j * 8 + 2 * t;
            #pragma unroll
            for (int q = 0; q < 4; q++) {
                int lr = lr0 + (q >> 1) * 8;
                int c  = c0 + (q & 1);
                float val = acc[i][j][q] + bias[c];
                if (MODE == 0) {
                    int n = tyl * 128 + lr;
                    int h = c >> 6, d = c & 63;
                    float sval = (z == 0) ? val : __uint_as_float(f2tf(val));
                    outp[(((size_t)(bb * HEADS + h)) * 1024 + n) * 64 + d] = sval;
                } else {
                    int r = m0 + lr;
                    float xv = (g_O[(size_t)r * 512 + c] - g_mu[r]) * g_rs[r]
                               * gamma[c] + beta[c];
                    outp[(size_t)r * 512 + c] = xv + fmaxf(val, 0.f);
                }
            }
        }
    }
}

// ---------------- fused flash attention (4-stage cp.async) -----------------
#define KSTRIDE 68
#define VSTRIDE 72
#define FSTAGES 4
#define KS_OFF 0
#define VS_OFF (FSTAGES*32*KSTRIDE)
#define PS_OFF (VS_OFF + FSTAGES*32*VSTRIDE)
#define SMEM_FLASH ((PS_OFF + 8*32*24) * 4)

__global__ void __launch_bounds__(256) flash_attn()
{
    extern __shared__ unsigned sm[];
    const unsigned smem_u32 = smem_cast(sm);

    const int bh = blockIdx.y;
    const int b = bh >> 3, h = bh & 7;
    const int i0 = blockIdx.x * 128;
    const int tid = threadIdx.x;
    const int warp = tid >> 5, lane = tid & 31;
    const int g = lane >> 2, t = lane & 3;

    const int nk = g_cnt[b];
    const int nchunks = (nk + 31) >> 5;
    const float* kbase = g_k + (size_t)bh * 1024 * 64;
    const float* vbase = g_v + (size_t)bh * 1024 * 64;
    const float scale = 0.044194173824159216f; // 1/sqrt(512)

    const float* qbase = g_q + ((size_t)bh * 1024 + i0 + warp * 16) * 64;
    unsigned qa[8][4];
    #pragma unroll
    for (int k = 0; k < 8; k++) {
        qa[k][0] = f2tf(qbase[(g    ) * 64 + k * 8 + t    ] * scale);
        qa[k][1] = f2tf(qbase[(g + 8) * 64 + k * 8 + t    ] * scale);
        qa[k][2] = f2tf(qbase[(g    ) * 64 + k * 8 + t + 4] * scale);
        qa[k][3] = f2tf(qbase[(g + 8) * 64 + k * 8 + t + 4] * scale);
    }

    auto issue_load = [&](int ch) {
        int bufi = ch & 3;
        unsigned Kb = smem_u32 + (KS_OFF + bufi * 32 * KSTRIDE) * 4;
        unsigned Vb = smem_u32 + (VS_OFF + bufi * 32 * VSTRIDE) * 4;
        #pragma unroll
        for (int it = 0; it < 2; it++) {
            int i = tid + it * 256;
            int key = i >> 4;
            int dc = (i & 15) << 2;
            int gkey = ch * 32 + key;
            int sz = (gkey < nk) ? 16 : 0;
            cp16(Kb + (key * KSTRIDE + dc) * 4, kbase + (size_t)gkey * 64 + dc, sz);
            cp16(Vb + (key * VSTRIDE + dc) * 4, vbase + (size_t)gkey * 64 + dc, sz);
        }
        asm volatile("cp.async.commit_group;\n");
    };

    float oacc[8][4];
    #pragma unroll
    for (int n = 0; n < 8; n++)
        #pragma unroll
        for (int j = 0; j < 4; j++) oacc[n][j] = 0.f;
    float mrow0 = -1e30f, mrow1 = -1e30f;
    float lrow0 = 0.f,    lrow1 = 0.f;

    unsigned* Pw = sm + PS_OFF + warp * 768;

    issue_load(0);
    if (nchunks > 1) issue_load(1); else asm volatile("cp.async.commit_group;\n");

    for (int ch = 0; ch < nchunks; ch++) {
        const int cur = ch & 3;
        if (ch + 2 < nchunks) issue_load(ch + 2);
        else asm volatile("cp.async.commit_group;\n");
        asm volatile("cp.async.wait_group 2;\n");
        __syncthreads();

        const unsigned* Kb = sm + KS_OFF + cur * 32 * KSTRIDE;
        const unsigned* Vb = sm + VS_OFF + cur * 32 * VSTRIDE;
        const int j0 = ch * 32;

        float sc[4][4];
        #pragma unroll
        for (int n = 0; n < 4; n++)
            #pragma unroll
            for (int j = 0; j < 4; j++) sc[n][j] = 0.f;
        #pragma unroll
        for (int k = 0; k < 8; k++) {
            #pragma unroll
            for (int n = 0; n < 4; n++) {
                unsigned b0 = Kb[(n * 8 + g) * KSTRIDE + k * 8 + t    ];
                unsigned b1 = Kb[(n * 8 + g) * KSTRIDE + k * 8 + t + 4];
                mma_tf32(sc[n], qa[k][0], qa[k][1], qa[k][2], qa[k][3], b0, b1);
            }
        }

        float mx0 = -1e30f, mx1 = -1e30f;
        #pragma unroll
        for (int n = 0; n < 4; n++) {
            int c0 = j0 + n * 8 + 2 * t;
            bool ok0 = c0 < nk, ok1 = (c0 + 1) < nk;
            float v0 = ok0 ? sc[n][0] : -10000.0f;
            float v1 = ok1 ? sc[n][1] : -10000.0f;
            float v2 = ok0 ? sc[n][2] : -10000.0f;
            float v3 = ok1 ? sc[n][3] : -10000.0f;
            sc[n][0] = v0; sc[n][1] = v1; sc[n][2] = v2; sc[n][3] = v3;
            mx0 = fmaxf(mx0, fmaxf(v0, v1));
            mx1 = fmaxf(mx1, fmaxf(v2, v3));
        }
        mx0 = fmaxf(mx0, __shfl_xor_sync(0xffffffffu, mx0, 1));
        mx0 = fmaxf(mx0, __shfl_xor_sync(0xffffffffu, mx0, 2));
        mx1 = fmaxf(mx1, __shfl_xor_sync(0xffffffffu, mx1, 1));
        mx1 = fmaxf(mx1, __shfl_xor_sync(0xffffffffu, mx1, 2));

        float mn0 = fmaxf(mrow0, mx0), mn1 = fmaxf(mrow1, mx1);
        float f0 = __expf(mrow0 - mn0), f1 = __expf(mrow1 - mn1);
        float s0 = 0.f, s1 = 0.f;
        #pragma unroll
        for (int n = 0; n < 4; n++) {
            float p0 = __expf(sc[n][0] - mn0);
            float p1 = __expf(sc[n][1] - mn0);
            float p2 = __expf(sc[n][2] - mn1);
            float p3 = __expf(sc[n][3] - mn1);
            s0 += p0 + p1; s1 += p2 + p3;
            Pw[(n * 8 + 2 * t    ) * 24 + g    ] = __float_as_uint(p0);
            Pw[(n * 8 + 2 * t + 1) * 24 + g    ] = __float_as_uint(p1);
            Pw[(n * 8 + 2 * t    ) * 24 + g + 8] = __float_as_uint(p2);
            Pw[(n * 8 + 2 * t + 1) * 24 + g + 8] = __float_as_uint(p3);
        }
        s0 += __shfl_xor_sync(0xffffffffu, s0, 1);
        s0 += __shfl_xor_sync(0xffffffffu, s0, 2);
        s1 += __shfl_xor_sync(0xffffffffu, s1, 1);
        s1 += __shfl_xor_sync(0xffffffffu, s1, 2);

        lrow0 = lrow0 * f0 + s0;
        lrow1 = lrow1 * f1 + s1;
        mrow0 = mn0; mrow1 = mn1;
        #pragma unroll
        for (int n = 0; n < 8; n++) {
            oacc[n][0] *= f0; oacc[n][1] *= f0;
            oacc[n][2] *= f1; oacc[n][3] *= f1;
        }
        __syncwarp();

        #pragma unroll
        for (int k = 0; k < 4; k++) {
            unsigned a0 = Pw[(k * 8 + t    ) * 24 + g    ];
            unsigned a1 = Pw[(k * 8 + t    ) * 24 + g + 8];
            unsigned a2 = Pw[(k * 8 + t + 4) * 24 + g    ];
            unsigned a3 = Pw[(k * 8 + t + 4) * 24 + g + 8];
            #pragma unroll
            for (int n = 0; n < 8; n++) {
                unsigned b0 = Vb[(k * 8 + t    ) * VSTRIDE + n * 8 + g];
                unsigned b1 = Vb[(k * 8 + t + 4) * VSTRIDE + n * 8 + g];
                mma_tf32(oacc[n], a0, a1, a2, a3, b0, b1);
            }
        }
    }

    // epilogue: write g_O and per-(row,head) LN0 partial sums
    float r0 = 1.0f / lrow0, r1 = 1.0f / lrow1;
    int row0 = i0 + warp * 16 + g;
    int row1 = row0 + 8;
    float* o0 = g_O + ((size_t)(b * 1024 + row0)) * 512 + h * 64;
    float* o1 = g_O + ((size_t)(b * 1024 + row1)) * 512 + h * 64;
    float s0 = 0.f, q0 = 0.f, s1 = 0.f, q1 = 0.f;
    #pragma unroll
    for (int n = 0; n < 8; n++) {
        int d = n * 8 + 2 * t;
        float v00 = oacc[n][0] * r0 + qbase[(g    ) * 64 + d    ];
        float v01 = oacc[n][1] * r0 + qbase[(g    ) * 64 + d + 1];
        float v10 = oacc[n][2] * r1 + qbase[(g + 8) * 64 + d    ];
        float v11 = oacc[n][3] * r1 + qbase[(g + 8) * 64 + d + 1];
        o0[d] = v00; o0[d + 1] = v01;
        o1[d] = v10; o1[d + 1] = v11;
        s0 += v00 + v01; q0 += v00 * v00 + v01 * v01;
        s1 += v10 + v11; q1 += v10 * v10 + v11 * v11;
    }
    s0 += __shfl_xor_sync(0xffffffffu, s0, 1);
    s0 += __shfl_xor_sync(0xffffffffu, s0, 2);
    q0 += __shfl_xor_sync(0xffffffffu, q0, 1);
    q0 += __shfl_xor_sync(0xffffffffu, q0, 2);
    s1 += __shfl_xor_sync(0xffffffffu, s1, 1);
    s1 += __shfl_xor_sync(0xffffffffu, s1, 2);
    q1 += __shfl_xor_sync(0xffffffffu, q1, 1);
    q1 += __shfl_xor_sync(0xffffffffu, q1, 2);
    if (t == 0) {
        g_part[b * 1024 + row0][h][0] = s0;
        g_part[b * 1024 + row0][h][1] = q0;
        g_part[b * 1024 + row1][h][0] = s1;
        g_part[b * 1024 + row1][h][1] = q1;
    }
}

// ---------------- LN0 stats finalize (from per-head partials) --------------
__global__ void ln_stats()
{
    int row = blockIdx.x * 256 + threadIdx.x;
    float s = 0.f, q = 0.f;
    #pragma unroll
    for (int h = 0; h < HEADS; h++) {
        s += g_part[row][h][0];
        q += g_part[row][h][1];
    }
    float mu = s * (1.f / 512.f);
    float var = q * (1.f / 512.f) - mu * mu;
    g_mu[row] = mu;
    g_rs[row] = rsqrtf(var + 1e-5f);
}

// ---------------- final LayerNorm: g_U -> out --------------------------------
__global__ void ln_final(const float* __restrict__ gg, const float* __restrict__ bb,
                         float* __restrict__ out)
{
    __shared__ float red[4];
    const int row = blockIdx.x, t = threadIdx.x;
    const float* p = g_U + (size_t)row * 512;
    float v[4];
    #pragma unroll
    for (int i = 0; i < 4; i++) v[i] = p[t + 128 * i];

    float s = v[0] + v[1] + v[2] + v[3];
    #pragma unroll
    for (int o = 16; o > 0; o >>= 1) s += __shfl_xor_sync(0xffffffffu, s, o);
    if ((t & 31) == 0) red[t >> 5] = s;
    __syncthreads();
    s = red[0] + red[1] + red[2] + red[3];
    float mean = s * (1.f / 512.f);
    __syncthreads();

    float ss = 0.f;
    #pragma unroll
    for (int i = 0; i < 4; i++) { float d = v[i] - mean; ss += d * d; }
    #pragma unroll
    for (int o = 16; o > 0; o >>= 1) ss += __shfl_xor_sync(0xffffffffu, ss, o);
    if ((t & 31) == 0) red[t >> 5] = ss;
    __syncthreads();
    ss = red[0] + red[1] + red[2] + red[3];
    float inv = rsqrtf(ss * (1.f / 512.f) + 1e-5f);

    #pragma unroll
    for (int i = 0; i < 4; i++) {
        int c = t + 128 * i;
        out[(size_t)row * 512 + c] = (v[i] - mean) * inv * gg[c] + bb[c];
    }
}

// ---------------- launch ----------------------------------------------------
extern "C" void kernel_launch(void* const* d_in, const int* in_sizes, int n_in,
                              void* d_out, int out_size)
{
    const float* Q    = (const float*)d_in[0];
    const float* K    = (const float*)d_in[1];
    const int*   mask = (const int*)  d_in[2];
    const float* Wq   = (const float*)d_in[3];
    const float* bq   = (const float*)d_in[4];
    const float* Wk   = (const float*)d_in[5];
    const float* bk   = (const float*)d_in[6];
    const float* Wv   = (const float*)d_in[7];
    const float* bv   = (const float*)d_in[8];
    const float* Wo   = (const float*)d_in[9];
    const float* bo   = (const float*)d_in[10];
    const float* g0   = (const float*)d_in[11];
    const float* b0   = (const float*)d_in[12];
    const float* g1   = (const float*)d_in[13];
    const float* b1   = (const float*)d_in[14];
    float* out = (float*)d_out;

    static bool attr_set = false;
    if (!attr_set) {
        cudaFuncSetAttribute(flash_attn, cudaFuncAttributeMaxDynamicSharedMemorySize,
                             SMEM_FLASH);
        cudaFuncSetAttribute(gemm128<0>, cudaFuncAttributeMaxDynamicSharedMemorySize,
                             GEMM_SMEM);
        cudaFuncSetAttribute(gemm128<1>, cudaFuncAttributeMaxDynamicSharedMemorySize,
                             GEMM_SMEM);
        attr_set = true;
    }

    compact_mask<<<BATCH, 1024>>>(mask);

    dim3 gqkv(DIM / 128, MROWS / 128, 3);   // (4, 64, 3)
    gemm128<0><<<gqkv, 256, GEMM_SMEM>>>(Q, K, Wq, bq, Wk, bk, Wv, bv);

    dim3 gf(NQ / 128, BH);                  // (8, 64)
    flash_attn<<<gf, 256, SMEM_FLASH>>>();

    ln_stats<<<MROWS / 256, 256>>>();

    dim3 go(DIM / 128, MROWS / 128, 1);     // (4, 64)
    gemm128<1><<<go, 256, GEMM_SMEM>>>(nullptr, nullptr, Wo, bo, g0, b0, nullptr, nullptr);

    ln_final<<<MROWS, 128>>>(g1, b1, out);
}